// round 13
// baseline (speedup 1.0000x reference)
#include <cuda_runtime.h>
#include <cuda_bf16.h>
#include <mma.h>
#include <math.h>
#include <stdint.h>

using namespace nvcuda;

#define Bb 4
#define Ss 2048
#define Dd 1024
#define Hh 16
#define DKk 64
#define EPSf 1e-6f
#define NEG_BIG -3.402823466e38f

// ==================== scratch (device globals) =============================
__device__ __align__(16) float g_bias[Hh*Ss];
__device__ __align__(16) __nv_bfloat16 g_a1[Bb*Ss*Dd];    // normed hi/lo
__device__ __align__(16) __nv_bfloat16 g_a2[Bb*Ss*Dd];
__device__ __align__(16) __nv_bfloat16 g_wq1[3072*Dd];    // W_qkv^T [n][k]
__device__ __align__(16) __nv_bfloat16 g_wq2[3072*Dd];
__device__ __align__(16) __nv_bfloat16 g_wo1[Dd*Dd];      // W_o^T [n][k]
__device__ __align__(16) __nv_bfloat16 g_wo2[Dd*Dd];
__device__ __align__(16) __nv_bfloat16 g_c1[Bb*Ss*Dd];    // ctx
__device__ __align__(16) __nv_bfloat16 g_c2[Bb*Ss*Dd];
__device__ __align__(16) __nv_bfloat16 g_q1[Bb*Hh*Ss*DKk];
__device__ __align__(16) __nv_bfloat16 g_q2[Bb*Hh*Ss*DKk];
__device__ __align__(16) __nv_bfloat16 g_k1[Bb*Hh*Ss*DKk];
__device__ __align__(16) __nv_bfloat16 g_k2[Bb*Hh*Ss*DKk];
__device__ __align__(16) __nv_bfloat16 g_v1[Bb*Hh*Ss*DKk];
__device__ __align__(16) __nv_bfloat16 g_v2[Bb*Hh*Ss*DKk];

// ==================== helpers ==============================================
__device__ __forceinline__ void split2(float va, float vb, uint32_t& hi2, uint32_t& lo2) {
    __nv_bfloat16 ha = __float2bfloat16(va);
    __nv_bfloat16 hb = __float2bfloat16(vb);
    __nv_bfloat16 la = __float2bfloat16(va - __bfloat162float(ha));
    __nv_bfloat16 lb = __float2bfloat16(vb - __bfloat162float(hb));
    hi2 = (uint32_t)__bfloat16_as_ushort(ha) | ((uint32_t)__bfloat16_as_ushort(hb) << 16);
    lo2 = (uint32_t)__bfloat16_as_ushort(la) | ((uint32_t)__bfloat16_as_ushort(lb) << 16);
}
__device__ __forceinline__ uint32_t smem_u32(const void* p) {
    uint32_t a;
    asm("{ .reg .u64 t; cvta.to.shared.u64 t, %1; cvt.u32.u64 %0, t; }" : "=r"(a) : "l"(p));
    return a;
}
__device__ __forceinline__ void cpa16(uint32_t s, const void* g) {
    asm volatile("cp.async.cg.shared.global [%0], [%1], 16;" :: "r"(s), "l"(g) : "memory");
}
#define CP_COMMIT() asm volatile("cp.async.commit_group;" ::: "memory")
#define CP_WAIT0()  asm volatile("cp.async.wait_group 0;" ::: "memory")
#define CP_WAIT1()  asm volatile("cp.async.wait_group 1;" ::: "memory")

// ==================== K0: RMSNorm -> split pairs ===========================
__global__ void __launch_bounds__(256) rmsnorm_kernel(const float* __restrict__ x,
                                                      const float* __restrict__ w) {
    int row = blockIdx.x;
    const float* xr = x + (size_t)row * Dd;
    float local = 0.f;
    for (int i = threadIdx.x; i < Dd; i += 256) { float v = xr[i]; local += v * v; }
    __shared__ float red[8];
    #pragma unroll
    for (int o = 16; o; o >>= 1) local += __shfl_xor_sync(0xffffffffu, local, o);
    if ((threadIdx.x & 31) == 0) red[threadIdx.x >> 5] = local;
    __syncthreads();
    if (threadIdx.x < 8) {
        float v = red[threadIdx.x];
        #pragma unroll
        for (int o = 4; o; o >>= 1) v += __shfl_xor_sync(0xffu, v, o);
        if (threadIdx.x == 0) red[0] = v;
    }
    __syncthreads();
    float scale = rsqrtf(red[0] * (1.0f / Dd) + EPSf);
    for (int i = threadIdx.x * 2; i < Dd; i += 512) {
        float y0 = xr[i] * scale * w[i];
        float y1 = xr[i + 1] * scale * w[i + 1];
        uint32_t hi, lo; split2(y0, y1, hi, lo);
        size_t off = (size_t)row * Dd + i;
        *(uint32_t*)(g_a1 + off) = hi;
        *(uint32_t*)(g_a2 + off) = lo;
    }
}

// ==================== K1: bias table =======================================
__global__ void bias_table_kernel(const float* __restrict__ rel_bias) {
    int d = blockIdx.x * blockDim.x + threadIdx.x;
    int h = blockIdx.y;
    if (d >= Ss) return;
    int bucket;
    if (d < 16) bucket = d;
    else {
        bucket = 16 + (int)(logf((float)d / 16.0f) / logf(8.0f) * 16.0f);
        if (bucket > 31) bucket = 31;
    }
    g_bias[h * Ss + d] = rel_bias[bucket * Hh + h];
}

// ==================== K2: weight transpose + split =========================
__device__ __forceinline__ void tsplit_body(const float* __restrict__ in,
                                            __nv_bfloat16* o1, __nv_bfloat16* o2,
                                            int K, int N) {
    __shared__ float t[32][33];
    int n0 = blockIdx.x * 32, k0 = blockIdx.y * 32;
    int tx = threadIdx.x & 31, ty = threadIdx.x >> 5;
    #pragma unroll
    for (int j = 0; j < 32; j += 8)
        t[ty + j][tx] = in[(size_t)(k0 + ty + j) * N + n0 + tx];
    __syncthreads();
    int tid = threadIdx.x;
    #pragma unroll
    for (int it = 0; it < 2; it++) {
        int p = it * 256 + tid;
        int nn = p >> 4, kp = (p & 15) * 2;
        float v0 = t[kp][nn];
        float v1 = t[kp + 1][nn];
        uint32_t hi, lo; split2(v0, v1, hi, lo);
        size_t off = (size_t)(n0 + nn) * K + k0 + kp;
        *(uint32_t*)(o1 + off) = hi;
        *(uint32_t*)(o2 + off) = lo;
    }
}
__global__ void __launch_bounds__(256) tsplit_wq_kernel(const float* __restrict__ in) {
    tsplit_body(in, g_wq1, g_wq2, Dd, 3072);
}
__global__ void __launch_bounds__(256) tsplit_wo_kernel(const float* __restrict__ in) {
    tsplit_body(in, g_wo1, g_wo2, Dd, Dd);
}

// ==================== WMMA GEMM core (pre-split inputs) ====================
#define ROWK 72
#define ARRE (128 * ROWK)
#define DYN_SMEM (4 * ARRE * 2)

typedef wmma::fragment<wmma::accumulator, 16, 16, 16, float> AccFrag;

__device__ __forceinline__ void gemm_wmma_mainloop2(
    const __nv_bfloat16* __restrict__ A1g, const __nv_bfloat16* __restrict__ A2g,
    const __nv_bfloat16* __restrict__ B1g, const __nv_bfloat16* __restrict__ B2g,
    char* dyn, AccFrag acc[4][2])
{
    int tid = threadIdx.x;
    int w = tid >> 5;
    int wm = w >> 2, wn = w & 3;
    __nv_bfloat16* sA1 = (__nv_bfloat16*)dyn;
    __nv_bfloat16* sA2 = sA1 + ARRE;
    __nv_bfloat16* sB1 = sA2 + ARRE;
    __nv_bfloat16* sB2 = sB1 + ARRE;

    for (int ch = 0; ch < Dd / 64; ch++) {
        const __nv_bfloat16* gsrc[4] = { A1g, A2g, B1g, B2g };
        __nv_bfloat16* sdst[4] = { sA1, sA2, sB1, sB2 };
        #pragma unroll
        for (int a = 0; a < 4; a++) {
            const __nv_bfloat16* g = gsrc[a] + ch * 64;
            __nv_bfloat16* s = sdst[a];
            #pragma unroll
            for (int i = 0; i < 4; i++) {
                int idx = i * 256 + tid;
                int row = idx >> 3, c8 = (idx & 7) * 8;
                *(uint4*)(s + row * ROWK + c8) =
                    *(const uint4*)(g + (size_t)row * Dd + c8);
            }
        }
        __syncthreads();
        #pragma unroll
        for (int kk = 0; kk < 4; kk++) {
            wmma::fragment<wmma::matrix_b, 16, 16, 16, __nv_bfloat16, wmma::col_major> b1[2], b2[2];
            #pragma unroll
            for (int u = 0; u < 2; u++) {
                int nb = (wn * 32 + u * 16) * ROWK + kk * 16;
                wmma::load_matrix_sync(b1[u], sB1 + nb, ROWK);
                wmma::load_matrix_sync(b2[u], sB2 + nb, ROWK);
            }
            #pragma unroll
            for (int t = 0; t < 4; t++) {
                wmma::fragment<wmma::matrix_a, 16, 16, 16, __nv_bfloat16, wmma::row_major> a1, a2;
                int ab = (wm * 64 + t * 16) * ROWK + kk * 16;
                wmma::load_matrix_sync(a1, sA1 + ab, ROWK);
                wmma::load_matrix_sync(a2, sA2 + ab, ROWK);
                #pragma unroll
                for (int u = 0; u < 2; u++) {
                    wmma::mma_sync(acc[t][u], a1, b1[u], acc[t][u]);
                    wmma::mma_sync(acc[t][u], a1, b2[u], acc[t][u]);
                    wmma::mma_sync(acc[t][u], a2, b1[u], acc[t][u]);
                }
            }
        }
        __syncthreads();
    }
}

// ---------------- QKV GEMM with split epilogue -----------------------------
__global__ void __launch_bounds__(256, 2) qkv_wmma_kernel() {
    extern __shared__ char dyn[];
    AccFrag acc[4][2];
    #pragma unroll
    for (int t = 0; t < 4; t++)
        #pragma unroll
        for (int u = 0; u < 2; u++) wmma::fill_fragment(acc[t][u], 0.0f);

    int n0 = blockIdx.x * 128, m0 = blockIdx.y * 128;
    gemm_wmma_mainloop2(g_a1 + (size_t)m0 * Dd, g_a2 + (size_t)m0 * Dd,
                        g_wq1 + (size_t)n0 * Dd, g_wq2 + (size_t)n0 * Dd, dyn, acc);

    float* ep = (float*)dyn;
    int w = threadIdx.x >> 5;
    int wm = w >> 2, wn = w & 3;
    #pragma unroll
    for (int t = 0; t < 4; t++)
        #pragma unroll
        for (int u = 0; u < 2; u++)
            wmma::store_matrix_sync(ep + (wm * 64 + t * 16) * 132 + wn * 32 + u * 16,
                                    acc[t][u], 132, wmma::mem_row_major);
    __syncthreads();

    int which = n0 >> 10;
    __nv_bfloat16* d1 = (which == 0) ? g_q1 : (which == 1) ? g_k1 : g_v1;
    __nv_bfloat16* d2 = (which == 0) ? g_q2 : (which == 1) ? g_k2 : g_v2;
    #pragma unroll
    for (int it = 0; it < 32; it++) {
        int p = it * 256 + threadIdx.x;
        int row = p >> 6, pr = p & 63;
        float a = ep[row * 132 + pr * 2];
        float b2v = ep[row * 132 + pr * 2 + 1];
        uint32_t hi, lo; split2(a, b2v, hi, lo);
        int n = n0 + pr * 2;
        int h = (n >> 6) & 15, dk0 = n & 63;
        int m = m0 + row, bb = m >> 11, s = m & 2047;
        size_t off = (((size_t)(bb * Hh + h)) * Ss + s) * DKk + dk0;
        *(uint32_t*)(d1 + off) = hi;
        *(uint32_t*)(d2 + off) = lo;
    }
}

// ---------------- out GEMM + residual --------------------------------------
__global__ void __launch_bounds__(256, 2) out_wmma_kernel(const float* __restrict__ hidden,
                                                          float* __restrict__ out) {
    extern __shared__ char dyn[];
    AccFrag acc[4][2];
    #pragma unroll
    for (int t = 0; t < 4; t++)
        #pragma unroll
        for (int u = 0; u < 2; u++) wmma::fill_fragment(acc[t][u], 0.0f);

    int n0 = blockIdx.x * 128, m0 = blockIdx.y * 128;
    gemm_wmma_mainloop2(g_c1 + (size_t)m0 * Dd, g_c2 + (size_t)m0 * Dd,
                        g_wo1 + (size_t)n0 * Dd, g_wo2 + (size_t)n0 * Dd, dyn, acc);

    int w = threadIdx.x >> 5;
    int wm = w >> 2, wn = w & 3;
    #pragma unroll
    for (int t = 0; t < 4; t++) {
        int m_sub = m0 + wm * 64 + t * 16;
        #pragma unroll
        for (int u = 0; u < 2; u++) {
            int n_sub = n0 + wn * 32 + u * 16;
            AccFrag hfrag;
            wmma::load_matrix_sync(hfrag, hidden + (size_t)m_sub * Dd + n_sub, Dd,
                                   wmma::mem_row_major);
            #pragma unroll
            for (int e = 0; e < hfrag.num_elements; e++)
                acc[t][u].x[e] += hfrag.x[e];
            wmma::store_matrix_sync(out + (size_t)m_sub * Dd + n_sub, acc[t][u], Dd,
                                    wmma::mem_row_major);
        }
    }
}

// ==================== K3: WMMA flash attention v7 (cp.async pipelined) =====
#define AQ1 0
#define AQ2 18432
#define AK1 36864
#define AK2 55296
#define AV1 73728
#define AV2 92160
#define AS  110592
#define AP1 178176
#define AP2 196608
#define ABI 215040
#define ATT_SMEM 216064

__global__ void __launch_bounds__(256) attn_wmma_kernel() {
    extern __shared__ char dyn[];
    __nv_bfloat16* Q1 = (__nv_bfloat16*)(dyn + AQ1);   // [128][72]
    __nv_bfloat16* Q2 = (__nv_bfloat16*)(dyn + AQ2);
    __nv_bfloat16* K1 = (__nv_bfloat16*)(dyn + AK1);   // [128][72]
    __nv_bfloat16* K2 = (__nv_bfloat16*)(dyn + AK2);
    __nv_bfloat16* V1 = (__nv_bfloat16*)(dyn + AV1);   // [128][72]
    __nv_bfloat16* V2 = (__nv_bfloat16*)(dyn + AV2);
    float* S = (float*)(dyn + AS);                     // [128][132]
    __nv_bfloat16* P1 = (__nv_bfloat16*)(dyn + AP1);   // [128][72]
    __nv_bfloat16* P2 = (__nv_bfloat16*)(dyn + AP2);
    float* bias_s = (float*)(dyn + ABI);               // [255]

    int tid = threadIdx.x;
    int w = tid >> 5;
    int wm = w >> 2, wn = w & 3;       // QK: 64q x 32kv
    int wm2 = w >> 1, wn2 = w & 1;     // PV: 32q x 32d
    int r = tid >> 1, half = tid & 1;
    int qb = gridDim.x - 1 - blockIdx.x;
    int q0 = qb * 128;
    int h  = blockIdx.y;
    int b  = blockIdx.z;
    size_t hoff = ((size_t)(b * Hh + h)) * Ss * DKk;
    const __nv_bfloat16* Qg1 = g_q1 + hoff;
    const __nv_bfloat16* Qg2 = g_q2 + hoff;
    const __nv_bfloat16* Kg1 = g_k1 + hoff;
    const __nv_bfloat16* Kg2 = g_k2 + hoff;
    const __nv_bfloat16* Vg1 = g_v1 + hoff;
    const __nv_bfloat16* Vg2 = g_v2 + hoff;
    const float* biasH = g_bias + h * Ss;

    uint32_t uK1 = smem_u32(K1), uK2 = smem_u32(K2);
    uint32_t uV1 = smem_u32(V1), uV2 = smem_u32(V2);

    // per-thread staging coordinates (8 uint4 rows-of-8 per array, 4 iters)
    // stage Q (plain copies, once)
    #pragma unroll
    for (int i = 0; i < 4; i++) {
        int idx = i * 256 + tid;
        int row = idx >> 3, c8 = (idx & 7) * 8;
        *(uint4*)(Q1 + row * 72 + c8) = *(const uint4*)(Qg1 + (size_t)(q0 + row) * DKk + c8);
        *(uint4*)(Q2 + row * 72 + c8) = *(const uint4*)(Qg2 + (size_t)(q0 + row) * DKk + c8);
    }
    float Oreg[32];
    #pragma unroll
    for (int c = 0; c < 32; c++) Oreg[c] = 0.f;
    float m_r = -INFINITY, l_r = 0.f;

    int ntiles = qb + 1;

    // prologue: async-issue K(0) group then V(0) group
    #pragma unroll
    for (int i = 0; i < 4; i++) {
        int idx = i * 256 + tid;
        int row = idx >> 3, c8 = (idx & 7) * 8;
        uint32_t so = (uint32_t)(row * 72 + c8) * 2;
        size_t go = (size_t)row * DKk + c8;
        cpa16(uK1 + so, Kg1 + go);
        cpa16(uK2 + so, Kg2 + go);
    }
    CP_COMMIT();
    #pragma unroll
    for (int i = 0; i < 4; i++) {
        int idx = i * 256 + tid;
        int row = idx >> 3, c8 = (idx & 7) * 8;
        uint32_t so = (uint32_t)(row * 72 + c8) * 2;
        size_t go = (size_t)row * DKk + c8;
        cpa16(uV1 + so, Vg1 + go);
        cpa16(uV2 + so, Vg2 + go);
    }
    CP_COMMIT();

    for (int kt = 0; kt < ntiles; kt++) {
        int k0 = kt * 128;
        bool more = (kt + 1 < ntiles);
        // bias strip for this tile (plain stores; ordered by the sync below)
        if (tid < 255) {
            int dist = q0 - k0 - 127 + tid;
            bias_s[tid] = biasH[dist < 0 ? 0 : dist];
        }
        CP_WAIT1();          // K(kt) ready (V(kt) may still be in flight)
        __syncthreads();

        // ---- QK: warp tile 64q x 32kv ----
        {
            AccFrag sacc[4][2];
            #pragma unroll
            for (int t = 0; t < 4; t++)
                #pragma unroll
                for (int u = 0; u < 2; u++) wmma::fill_fragment(sacc[t][u], 0.0f);
            #pragma unroll
            for (int kk = 0; kk < 4; kk++) {
                wmma::fragment<wmma::matrix_b, 16, 16, 16, __nv_bfloat16, wmma::col_major> b1[2], b2[2];
                #pragma unroll
                for (int u = 0; u < 2; u++) {
                    int bb = (wn * 32 + u * 16) * 72 + kk * 16;
                    wmma::load_matrix_sync(b1[u], K1 + bb, 72);
                    wmma::load_matrix_sync(b2[u], K2 + bb, 72);
                }
                #pragma unroll
                for (int t = 0; t < 4; t++) {
                    wmma::fragment<wmma::matrix_a, 16, 16, 16, __nv_bfloat16, wmma::row_major> a1, a2;
                    int ab = (wm * 64 + t * 16) * 72 + kk * 16;
                    wmma::load_matrix_sync(a1, Q1 + ab, 72);
                    wmma::load_matrix_sync(a2, Q2 + ab, 72);
                    #pragma unroll
                    for (int u = 0; u < 2; u++) {
                        wmma::mma_sync(sacc[t][u], a1, b1[u], sacc[t][u]);
                        wmma::mma_sync(sacc[t][u], a1, b2[u], sacc[t][u]);
                        wmma::mma_sync(sacc[t][u], a2, b1[u], sacc[t][u]);
                    }
                }
            }
            #pragma unroll
            for (int t = 0; t < 4; t++)
                #pragma unroll
                for (int u = 0; u < 2; u++)
                    wmma::store_matrix_sync(S + (wm * 64 + t * 16) * 132 + wn * 32 + u * 16,
                                            sacc[t][u], 132, wmma::mem_row_major);
        }
        __syncthreads();     // QK done: K buffer free, S visible

        // prefetch K(kt+1) — overlaps softmax + PV + O-update
        if (more) {
            int k0n = k0 + 128;
            #pragma unroll
            for (int i = 0; i < 4; i++) {
                int idx = i * 256 + tid;
                int row = idx >> 3, c8 = (idx & 7) * 8;
                uint32_t so = (uint32_t)(row * 72 + c8) * 2;
                size_t go = (size_t)(k0n + row) * DKk + c8;
                cpa16(uK1 + so, Kg1 + go);
                cpa16(uK2 + so, Kg2 + go);
            }
            CP_COMMIT();
        }

        // ---- pass1: bias+mask (float4 S), row max, rescale O ----
        {
            float* Srow = S + r * 132 + half * 64;
            int lim = r + q0 - k0;
            float mx = -INFINITY;
            #pragma unroll
            for (int c4 = 0; c4 < 64; c4 += 4) {
                float4 sv = *(float4*)(Srow + c4);
                int cc = half * 64 + c4;
                int bi = r - cc + 127;
                sv.x += bias_s[bi];     if (cc     > lim) sv.x = NEG_BIG;
                sv.y += bias_s[bi - 1]; if (cc + 1 > lim) sv.y = NEG_BIG;
                sv.z += bias_s[bi - 2]; if (cc + 2 > lim) sv.z = NEG_BIG;
                sv.w += bias_s[bi - 3]; if (cc + 3 > lim) sv.w = NEG_BIG;
                *(float4*)(Srow + c4) = sv;
                mx = fmaxf(mx, fmaxf(fmaxf(sv.x, sv.y), fmaxf(sv.z, sv.w)));
            }
            mx = fmaxf(mx, __shfl_xor_sync(0xffffffffu, mx, 1));
            float mnew = fmaxf(m_r, mx);
            float scale = __expf(m_r - mnew);
            m_r = mnew;
            l_r *= scale;
            #pragma unroll
            for (int c = 0; c < 32; c++) Oreg[c] *= scale;
        }
        // V(kt) must be resident before PV. Pending groups (commit order):
        // [V(kt), K(kt+1)?] — WAIT1 retires V(kt) if K(kt+1) in flight, else WAIT0.
        if (more) CP_WAIT1(); else CP_WAIT0();
        __syncthreads();

        float rowsum = 0.f;
        AccFrag oacc[2][2];
        #pragma unroll
        for (int t = 0; t < 2; t++)
            #pragma unroll
            for (int u = 0; u < 2; u++) wmma::fill_fragment(oacc[t][u], 0.0f);

        #pragma unroll
        for (int hf = 0; hf < 2; hf++) {
            // ---- pass2: exp + packed split into P ----
            {
                float* Sr = S + r * 132 + hf * 64 + half * 32;
                int pc0 = half * 32;
                #pragma unroll
                for (int c4 = 0; c4 < 32; c4 += 4) {
                    float4 sv = *(float4*)(Sr + c4);
                    float p0 = __expf(sv.x - m_r);
                    float p1 = __expf(sv.y - m_r);
                    float p2 = __expf(sv.z - m_r);
                    float p3 = __expf(sv.w - m_r);
                    rowsum += (p0 + p1) + (p2 + p3);
                    uint32_t h0, l0, h1, l1;
                    split2(p0, p1, h0, l0);
                    split2(p2, p3, h1, l1);
                    *(uint2*)(P1 + r * 72 + pc0 + c4) = make_uint2(h0, h1);
                    *(uint2*)(P2 + r * 72 + pc0 + c4) = make_uint2(l0, l1);
                }
            }
            __syncthreads();
            // ---- PV half: warp tile 32q x 32d ----
            #pragma unroll
            for (int kk = 0; kk < 4; kk++) {
                wmma::fragment<wmma::matrix_a, 16, 16, 16, __nv_bfloat16, wmma::row_major> a1[2], a2[2];
                #pragma unroll
                for (int t = 0; t < 2; t++) {
                    int ab = (wm2 * 32 + t * 16) * 72 + kk * 16;
                    wmma::load_matrix_sync(a1[t], P1 + ab, 72);
                    wmma::load_matrix_sync(a2[t], P2 + ab, 72);
                }
                #pragma unroll
                for (int u = 0; u < 2; u++) {
                    wmma::fragment<wmma::matrix_b, 16, 16, 16, __nv_bfloat16, wmma::row_major> b1, b2;
                    int bb = (hf * 64 + kk * 16) * 72 + wn2 * 32 + u * 16;
                    wmma::load_matrix_sync(b1, V1 + bb, 72);
                    wmma::load_matrix_sync(b2, V2 + bb, 72);
                    #pragma unroll
                    for (int t = 0; t < 2; t++) {
                        wmma::mma_sync(oacc[t][u], a1[t], b1, oacc[t][u]);
                        wmma::mma_sync(oacc[t][u], a1[t], b2, oacc[t][u]);
                        wmma::mma_sync(oacc[t][u], a2[t], b1, oacc[t][u]);
                    }
                }
            }
            __syncthreads();   // P consumed (hf) / V consumed (hf==1)
        }

        // prefetch V(kt+1) — V buffer free after the sync above
        if (more) {
            int k0n = k0 + 128;
            #pragma unroll
            for (int i = 0; i < 4; i++) {
                int idx = i * 256 + tid;
                int row = idx >> 3, c8 = (idx & 7) * 8;
                uint32_t so = (uint32_t)(row * 72 + c8) * 2;
                size_t go = (size_t)(k0n + row) * DKk + c8;
                cpa16(uV1 + so, Vg1 + go);
                cpa16(uV2 + so, Vg2 + go);
            }
            CP_COMMIT();
        }

        #pragma unroll
        for (int t = 0; t < 2; t++)
            #pragma unroll
            for (int u = 0; u < 2; u++)
                wmma::store_matrix_sync(S + (wm2 * 32 + t * 16) * 132 + wn2 * 32 + u * 16,
                                        oacc[t][u], 132, wmma::mem_row_major);
        rowsum += __shfl_xor_sync(0xffffffffu, rowsum, 1);
        l_r += rowsum;
        __syncthreads();
        {
            float* Sr = S + r * 132 + half * 32;
            #pragma unroll
            for (int c4 = 0; c4 < 32; c4 += 4) {
                float4 sv = *(float4*)(Sr + c4);
                Oreg[c4]     += sv.x;
                Oreg[c4 + 1] += sv.y;
                Oreg[c4 + 2] += sv.z;
                Oreg[c4 + 3] += sv.w;
            }
        }
        __syncthreads();   // S free before next tile's QK stores
    }

    // epilogue: ctx = O / l, written pre-split to g_c1/g_c2 [m][1024]
    float inv = 1.0f / l_r;
    size_t cbase = ((size_t)(b * Ss + q0 + r)) * Dd + h * DKk + half * 32;
    #pragma unroll
    for (int c4 = 0; c4 < 32; c4 += 4) {
        float v0 = Oreg[c4] * inv,     v1 = Oreg[c4 + 1] * inv;
        float v2 = Oreg[c4 + 2] * inv, v3 = Oreg[c4 + 3] * inv;
        uint32_t h0, l0, h1, l1;
        split2(v0, v1, h0, l0);
        split2(v2, v3, h1, l1);
        *(uint2*)(g_c1 + cbase + c4) = make_uint2(h0, h1);
        *(uint2*)(g_c2 + cbase + c4) = make_uint2(l0, l1);
    }
}

// ==================== launch ==============================================
extern "C" void kernel_launch(void* const* d_in, const int* in_sizes, int n_in,
                              void* d_out, int out_size) {
    const float* hidden   = (const float*)d_in[0];
    const float* rms_w    = (const float*)d_in[2];
    const float* W_qkv    = (const float*)d_in[3];
    const float* W_o      = (const float*)d_in[4];
    const float* rel_bias = (const float*)d_in[5];
    float* out = (float*)d_out;

    rmsnorm_kernel<<<Bb * Ss, 256>>>(hidden, rms_w);
    bias_table_kernel<<<dim3(Ss / 256, Hh), 256>>>(rel_bias);
    tsplit_wq_kernel<<<dim3(3072 / 32, Dd / 32), 256>>>(W_qkv);
    tsplit_wo_kernel<<<dim3(Dd / 32, Dd / 32), 256>>>(W_o);

    cudaFuncSetAttribute(qkv_wmma_kernel, cudaFuncAttributeMaxDynamicSharedMemorySize, DYN_SMEM);
    qkv_wmma_kernel<<<dim3(3072 / 128, (Bb * Ss) / 128), 256, DYN_SMEM>>>();

    cudaFuncSetAttribute(attn_wmma_kernel, cudaFuncAttributeMaxDynamicSharedMemorySize, ATT_SMEM);
    attn_wmma_kernel<<<dim3(Ss / 128, Hh, Bb), 256, ATT_SMEM>>>();

    cudaFuncSetAttribute(out_wmma_kernel, cudaFuncAttributeMaxDynamicSharedMemorySize, DYN_SMEM);
    out_wmma_kernel<<<dim3(Dd / 128, (Bb * Ss) / 128), 256, DYN_SMEM>>>(hidden, out);
}

// round 14
// speedup vs baseline: 1.5326x; 1.5326x over previous
#include <cuda_runtime.h>
#include <cuda_bf16.h>
#include <mma.h>
#include <math.h>
#include <stdint.h>

using namespace nvcuda;

#define Bb 4
#define Ss 2048
#define Dd 1024
#define Hh 16
#define DKk 64
#define EPSf 1e-6f
#define NEG_BIG -3.402823466e38f

// ==================== scratch (device globals) =============================
__device__ __align__(16) float g_bias[Hh*Ss];
__device__ __align__(16) __nv_bfloat16 g_a1[Bb*Ss*Dd];    // normed hi/lo
__device__ __align__(16) __nv_bfloat16 g_a2[Bb*Ss*Dd];
__device__ __align__(16) __nv_bfloat16 g_wq1[3072*Dd];    // W_qkv^T [n][k]
__device__ __align__(16) __nv_bfloat16 g_wq2[3072*Dd];
__device__ __align__(16) __nv_bfloat16 g_wo1[Dd*Dd];      // W_o^T [n][k]
__device__ __align__(16) __nv_bfloat16 g_wo2[Dd*Dd];
__device__ __align__(16) __nv_bfloat16 g_c1[Bb*Ss*Dd];    // ctx
__device__ __align__(16) __nv_bfloat16 g_c2[Bb*Ss*Dd];
__device__ __align__(16) __nv_bfloat16 g_q1[Bb*Hh*Ss*DKk];
__device__ __align__(16) __nv_bfloat16 g_q2[Bb*Hh*Ss*DKk];
__device__ __align__(16) __nv_bfloat16 g_k1[Bb*Hh*Ss*DKk];
__device__ __align__(16) __nv_bfloat16 g_k2[Bb*Hh*Ss*DKk];
__device__ __align__(16) __nv_bfloat16 g_v1[Bb*Hh*Ss*DKk];
__device__ __align__(16) __nv_bfloat16 g_v2[Bb*Hh*Ss*DKk];

// ==================== split helper (packed pair) ===========================
__device__ __forceinline__ void split2(float va, float vb, uint32_t& hi2, uint32_t& lo2) {
    __nv_bfloat16 ha = __float2bfloat16(va);
    __nv_bfloat16 hb = __float2bfloat16(vb);
    __nv_bfloat16 la = __float2bfloat16(va - __bfloat162float(ha));
    __nv_bfloat16 lb = __float2bfloat16(vb - __bfloat162float(hb));
    hi2 = (uint32_t)__bfloat16_as_ushort(ha) | ((uint32_t)__bfloat16_as_ushort(hb) << 16);
    lo2 = (uint32_t)__bfloat16_as_ushort(la) | ((uint32_t)__bfloat16_as_ushort(lb) << 16);
}

// ==================== K0: RMSNorm -> split pairs ===========================
__global__ void __launch_bounds__(256) rmsnorm_kernel(const float* __restrict__ x,
                                                      const float* __restrict__ w) {
    int row = blockIdx.x;
    const float* xr = x + (size_t)row * Dd;
    float local = 0.f;
    for (int i = threadIdx.x; i < Dd; i += 256) { float v = xr[i]; local += v * v; }
    __shared__ float red[8];
    #pragma unroll
    for (int o = 16; o; o >>= 1) local += __shfl_xor_sync(0xffffffffu, local, o);
    if ((threadIdx.x & 31) == 0) red[threadIdx.x >> 5] = local;
    __syncthreads();
    if (threadIdx.x < 8) {
        float v = red[threadIdx.x];
        #pragma unroll
        for (int o = 4; o; o >>= 1) v += __shfl_xor_sync(0xffu, v, o);
        if (threadIdx.x == 0) red[0] = v;
    }
    __syncthreads();
    float scale = rsqrtf(red[0] * (1.0f / Dd) + EPSf);
    for (int i = threadIdx.x * 2; i < Dd; i += 512) {
        float y0 = xr[i] * scale * w[i];
        float y1 = xr[i + 1] * scale * w[i + 1];
        uint32_t hi, lo; split2(y0, y1, hi, lo);
        size_t off = (size_t)row * Dd + i;
        *(uint32_t*)(g_a1 + off) = hi;
        *(uint32_t*)(g_a2 + off) = lo;
    }
}

// ==================== K1: bias table =======================================
__global__ void bias_table_kernel(const float* __restrict__ rel_bias) {
    int d = blockIdx.x * blockDim.x + threadIdx.x;
    int h = blockIdx.y;
    if (d >= Ss) return;
    int bucket;
    if (d < 16) bucket = d;
    else {
        bucket = 16 + (int)(logf((float)d / 16.0f) / logf(8.0f) * 16.0f);
        if (bucket > 31) bucket = 31;
    }
    g_bias[h * Ss + d] = rel_bias[bucket * Hh + h];
}

// ==================== K2: weight transpose + split =========================
__device__ __forceinline__ void tsplit_body(const float* __restrict__ in,
                                            __nv_bfloat16* o1, __nv_bfloat16* o2,
                                            int K, int N) {
    __shared__ float t[32][33];
    int n0 = blockIdx.x * 32, k0 = blockIdx.y * 32;
    int tx = threadIdx.x & 31, ty = threadIdx.x >> 5;
    #pragma unroll
    for (int j = 0; j < 32; j += 8)
        t[ty + j][tx] = in[(size_t)(k0 + ty + j) * N + n0 + tx];
    __syncthreads();
    int tid = threadIdx.x;
    #pragma unroll
    for (int it = 0; it < 2; it++) {
        int p = it * 256 + tid;
        int nn = p >> 4, kp = (p & 15) * 2;
        float v0 = t[kp][nn];
        float v1 = t[kp + 1][nn];
        uint32_t hi, lo; split2(v0, v1, hi, lo);
        size_t off = (size_t)(n0 + nn) * K + k0 + kp;
        *(uint32_t*)(o1 + off) = hi;
        *(uint32_t*)(o2 + off) = lo;
    }
}
__global__ void __launch_bounds__(256) tsplit_wq_kernel(const float* __restrict__ in) {
    tsplit_body(in, g_wq1, g_wq2, Dd, 3072);
}
__global__ void __launch_bounds__(256) tsplit_wo_kernel(const float* __restrict__ in) {
    tsplit_body(in, g_wo1, g_wo2, Dd, Dd);
}

// ==================== WMMA GEMM core (pre-split inputs) ====================
#define ROWK 72
#define ARRE (128 * ROWK)
#define DYN_SMEM (4 * ARRE * 2)

typedef wmma::fragment<wmma::accumulator, 16, 16, 16, float> AccFrag;

__device__ __forceinline__ void gemm_wmma_mainloop2(
    const __nv_bfloat16* __restrict__ A1g, const __nv_bfloat16* __restrict__ A2g,
    const __nv_bfloat16* __restrict__ B1g, const __nv_bfloat16* __restrict__ B2g,
    char* dyn, AccFrag acc[4][2])
{
    int tid = threadIdx.x;
    int w = tid >> 5;
    int wm = w >> 2, wn = w & 3;
    __nv_bfloat16* sA1 = (__nv_bfloat16*)dyn;
    __nv_bfloat16* sA2 = sA1 + ARRE;
    __nv_bfloat16* sB1 = sA2 + ARRE;
    __nv_bfloat16* sB2 = sB1 + ARRE;

    for (int ch = 0; ch < Dd / 64; ch++) {
        const __nv_bfloat16* gsrc[4] = { A1g, A2g, B1g, B2g };
        __nv_bfloat16* sdst[4] = { sA1, sA2, sB1, sB2 };
        #pragma unroll
        for (int a = 0; a < 4; a++) {
            const __nv_bfloat16* g = gsrc[a] + ch * 64;
            __nv_bfloat16* s = sdst[a];
            #pragma unroll
            for (int i = 0; i < 4; i++) {
                int idx = i * 256 + tid;
                int row = idx >> 3, c8 = (idx & 7) * 8;
                *(uint4*)(s + row * ROWK + c8) =
                    *(const uint4*)(g + (size_t)row * Dd + c8);
            }
        }
        __syncthreads();
        #pragma unroll
        for (int kk = 0; kk < 4; kk++) {
            wmma::fragment<wmma::matrix_b, 16, 16, 16, __nv_bfloat16, wmma::col_major> b1[2], b2[2];
            #pragma unroll
            for (int u = 0; u < 2; u++) {
                int nb = (wn * 32 + u * 16) * ROWK + kk * 16;
                wmma::load_matrix_sync(b1[u], sB1 + nb, ROWK);
                wmma::load_matrix_sync(b2[u], sB2 + nb, ROWK);
            }
            #pragma unroll
            for (int t = 0; t < 4; t++) {
                wmma::fragment<wmma::matrix_a, 16, 16, 16, __nv_bfloat16, wmma::row_major> a1, a2;
                int ab = (wm * 64 + t * 16) * ROWK + kk * 16;
                wmma::load_matrix_sync(a1, sA1 + ab, ROWK);
                wmma::load_matrix_sync(a2, sA2 + ab, ROWK);
                #pragma unroll
                for (int u = 0; u < 2; u++) {
                    wmma::mma_sync(acc[t][u], a1, b1[u], acc[t][u]);
                    wmma::mma_sync(acc[t][u], a1, b2[u], acc[t][u]);
                    wmma::mma_sync(acc[t][u], a2, b1[u], acc[t][u]);
                }
            }
        }
        __syncthreads();
    }
}

// ---------------- QKV GEMM with split epilogue -----------------------------
__global__ void __launch_bounds__(256, 2) qkv_wmma_kernel() {
    extern __shared__ char dyn[];
    AccFrag acc[4][2];
    #pragma unroll
    for (int t = 0; t < 4; t++)
        #pragma unroll
        for (int u = 0; u < 2; u++) wmma::fill_fragment(acc[t][u], 0.0f);

    int n0 = blockIdx.x * 128, m0 = blockIdx.y * 128;
    gemm_wmma_mainloop2(g_a1 + (size_t)m0 * Dd, g_a2 + (size_t)m0 * Dd,
                        g_wq1 + (size_t)n0 * Dd, g_wq2 + (size_t)n0 * Dd, dyn, acc);

    float* ep = (float*)dyn;
    int w = threadIdx.x >> 5;
    int wm = w >> 2, wn = w & 3;
    #pragma unroll
    for (int t = 0; t < 4; t++)
        #pragma unroll
        for (int u = 0; u < 2; u++)
            wmma::store_matrix_sync(ep + (wm * 64 + t * 16) * 132 + wn * 32 + u * 16,
                                    acc[t][u], 132, wmma::mem_row_major);
    __syncthreads();

    int which = n0 >> 10;
    __nv_bfloat16* d1 = (which == 0) ? g_q1 : (which == 1) ? g_k1 : g_v1;
    __nv_bfloat16* d2 = (which == 0) ? g_q2 : (which == 1) ? g_k2 : g_v2;
    #pragma unroll
    for (int it = 0; it < 32; it++) {
        int p = it * 256 + threadIdx.x;
        int row = p >> 6, pr = p & 63;
        float a = ep[row * 132 + pr * 2];
        float b2v = ep[row * 132 + pr * 2 + 1];
        uint32_t hi, lo; split2(a, b2v, hi, lo);
        int n = n0 + pr * 2;
        int h = (n >> 6) & 15, dk0 = n & 63;
        int m = m0 + row, bb = m >> 11, s = m & 2047;
        size_t off = (((size_t)(bb * Hh + h)) * Ss + s) * DKk + dk0;
        *(uint32_t*)(d1 + off) = hi;
        *(uint32_t*)(d2 + off) = lo;
    }
}

// ---------------- out GEMM + residual --------------------------------------
__global__ void __launch_bounds__(256, 2) out_wmma_kernel(const float* __restrict__ hidden,
                                                          float* __restrict__ out) {
    extern __shared__ char dyn[];
    AccFrag acc[4][2];
    #pragma unroll
    for (int t = 0; t < 4; t++)
        #pragma unroll
        for (int u = 0; u < 2; u++) wmma::fill_fragment(acc[t][u], 0.0f);

    int n0 = blockIdx.x * 128, m0 = blockIdx.y * 128;
    gemm_wmma_mainloop2(g_c1 + (size_t)m0 * Dd, g_c2 + (size_t)m0 * Dd,
                        g_wo1 + (size_t)n0 * Dd, g_wo2 + (size_t)n0 * Dd, dyn, acc);

    int w = threadIdx.x >> 5;
    int wm = w >> 2, wn = w & 3;
    #pragma unroll
    for (int t = 0; t < 4; t++) {
        int m_sub = m0 + wm * 64 + t * 16;
        #pragma unroll
        for (int u = 0; u < 2; u++) {
            int n_sub = n0 + wn * 32 + u * 16;
            AccFrag hfrag;
            wmma::load_matrix_sync(hfrag, hidden + (size_t)m_sub * Dd + n_sub, Dd,
                                   wmma::mem_row_major);
            #pragma unroll
            for (int e = 0; e < hfrag.num_elements; e++)
                acc[t][u].x[e] += hfrag.x[e];
            wmma::store_matrix_sync(out + (size_t)m_sub * Dd + n_sub, acc[t][u], Dd,
                                    wmma::mem_row_major);
        }
    }
}

// ==================== K3: WMMA flash attention v8 ==========================
// Round-12 structure + persistent O accumulator fragments (no per-tile
// O smem round-trip). Rescale applied per-element using the sm80+ wmma
// accumulator layout: x0,x1,x4,x5 -> row g ; x2,x3,x6,x7 -> row g+8.
#define AQ1 0
#define AQ2 18432
#define AK1 36864
#define AK2 55296
#define AV1 73728
#define AV2 92160
#define AS  110592
#define AP1 178176
#define AP2 196608
#define ABI 215040
#define ASCL 216064
#define ATT_SMEM 216576

__global__ void __launch_bounds__(256) attn_wmma_kernel() {
    extern __shared__ char dyn[];
    __nv_bfloat16* Q1 = (__nv_bfloat16*)(dyn + AQ1);   // [128][72]
    __nv_bfloat16* Q2 = (__nv_bfloat16*)(dyn + AQ2);
    __nv_bfloat16* K1 = (__nv_bfloat16*)(dyn + AK1);   // [128][72]
    __nv_bfloat16* K2 = (__nv_bfloat16*)(dyn + AK2);
    __nv_bfloat16* V1 = (__nv_bfloat16*)(dyn + AV1);   // [128][72]
    __nv_bfloat16* V2 = (__nv_bfloat16*)(dyn + AV2);
    float* S = (float*)(dyn + AS);                     // [128][132]
    __nv_bfloat16* P1 = (__nv_bfloat16*)(dyn + AP1);   // [128][72]
    __nv_bfloat16* P2 = (__nv_bfloat16*)(dyn + AP2);
    float* bias_s = (float*)(dyn + ABI);               // [255]
    float* scl = (float*)(dyn + ASCL);                 // [128] per-row rescale

    int tid = threadIdx.x;
    int w = tid >> 5;
    int lane = tid & 31;
    int g4 = lane >> 2;                // fragment row group
    int wm = w >> 2, wn = w & 3;       // QK: 64q x 32kv
    int wm2 = w >> 1, wn2 = w & 1;     // PV: 32q x 32d
    int r = tid >> 1, half = tid & 1;
    int qb = gridDim.x - 1 - blockIdx.x;
    int q0 = qb * 128;
    int h  = blockIdx.y;
    int b  = blockIdx.z;
    size_t hoff = ((size_t)(b * Hh + h)) * Ss * DKk;
    const __nv_bfloat16* Qg1 = g_q1 + hoff;
    const __nv_bfloat16* Qg2 = g_q2 + hoff;
    const __nv_bfloat16* Kg1 = g_k1 + hoff;
    const __nv_bfloat16* Kg2 = g_k2 + hoff;
    const __nv_bfloat16* Vg1 = g_v1 + hoff;
    const __nv_bfloat16* Vg2 = g_v2 + hoff;
    const float* biasH = g_bias + h * Ss;

    #pragma unroll
    for (int i = 0; i < 4; i++) {
        int idx = i * 256 + tid;
        int row = idx >> 3, c8 = (idx & 7) * 8;
        *(uint4*)(Q1 + row * 72 + c8) = *(const uint4*)(Qg1 + (size_t)(q0 + row) * DKk + c8);
        *(uint4*)(Q2 + row * 72 + c8) = *(const uint4*)(Qg2 + (size_t)(q0 + row) * DKk + c8);
    }
    float m_r = -INFINITY, l_r = 0.f;
    AccFrag oacc[2][2];                 // persistent across kv tiles
    #pragma unroll
    for (int t = 0; t < 2; t++)
        #pragma unroll
        for (int u = 0; u < 2; u++) wmma::fill_fragment(oacc[t][u], 0.0f);
    __syncthreads();

    int ntiles = qb + 1;
    for (int kt = 0; kt < ntiles; kt++) {
        int k0 = kt * 128;
        #pragma unroll
        for (int i = 0; i < 4; i++) {
            int idx = i * 256 + tid;
            int row = idx >> 3, c8 = (idx & 7) * 8;
            size_t goff = (size_t)(k0 + row) * DKk + c8;
            int soff = row * 72 + c8;
            *(uint4*)(K1 + soff) = *(const uint4*)(Kg1 + goff);
            *(uint4*)(K2 + soff) = *(const uint4*)(Kg2 + goff);
            *(uint4*)(V1 + soff) = *(const uint4*)(Vg1 + goff);
            *(uint4*)(V2 + soff) = *(const uint4*)(Vg2 + goff);
        }
        if (tid < 255) {
            int dist = q0 - k0 - 127 + tid;
            bias_s[tid] = biasH[dist < 0 ? 0 : dist];
        }
        __syncthreads();

        // ---- QK: warp tile 64q x 32kv ----
        {
            AccFrag sacc[4][2];
            #pragma unroll
            for (int t = 0; t < 4; t++)
                #pragma unroll
                for (int u = 0; u < 2; u++) wmma::fill_fragment(sacc[t][u], 0.0f);
            #pragma unroll
            for (int kk = 0; kk < 4; kk++) {
                wmma::fragment<wmma::matrix_b, 16, 16, 16, __nv_bfloat16, wmma::col_major> b1[2], b2[2];
                #pragma unroll
                for (int u = 0; u < 2; u++) {
                    int bb = (wn * 32 + u * 16) * 72 + kk * 16;
                    wmma::load_matrix_sync(b1[u], K1 + bb, 72);
                    wmma::load_matrix_sync(b2[u], K2 + bb, 72);
                }
                #pragma unroll
                for (int t = 0; t < 4; t++) {
                    wmma::fragment<wmma::matrix_a, 16, 16, 16, __nv_bfloat16, wmma::row_major> a1, a2;
                    int ab = (wm * 64 + t * 16) * 72 + kk * 16;
                    wmma::load_matrix_sync(a1, Q1 + ab, 72);
                    wmma::load_matrix_sync(a2, Q2 + ab, 72);
                    #pragma unroll
                    for (int u = 0; u < 2; u++) {
                        wmma::mma_sync(sacc[t][u], a1, b1[u], sacc[t][u]);
                        wmma::mma_sync(sacc[t][u], a1, b2[u], sacc[t][u]);
                        wmma::mma_sync(sacc[t][u], a2, b1[u], sacc[t][u]);
                    }
                }
            }
            #pragma unroll
            for (int t = 0; t < 4; t++)
                #pragma unroll
                for (int u = 0; u < 2; u++)
                    wmma::store_matrix_sync(S + (wm * 64 + t * 16) * 132 + wn * 32 + u * 16,
                                            sacc[t][u], 132, wmma::mem_row_major);
        }
        __syncthreads();

        // ---- pass1: bias+mask (float4 S), row max, publish rescale ----
        {
            float* Srow = S + r * 132 + half * 64;
            int lim = r + q0 - k0;
            float mx = -INFINITY;
            #pragma unroll
            for (int c4 = 0; c4 < 64; c4 += 4) {
                float4 sv = *(float4*)(Srow + c4);
                int cc = half * 64 + c4;
                int bi = r - cc + 127;
                sv.x += bias_s[bi];     if (cc     > lim) sv.x = NEG_BIG;
                sv.y += bias_s[bi - 1]; if (cc + 1 > lim) sv.y = NEG_BIG;
                sv.z += bias_s[bi - 2]; if (cc + 2 > lim) sv.z = NEG_BIG;
                sv.w += bias_s[bi - 3]; if (cc + 3 > lim) sv.w = NEG_BIG;
                *(float4*)(Srow + c4) = sv;
                mx = fmaxf(mx, fmaxf(fmaxf(sv.x, sv.y), fmaxf(sv.z, sv.w)));
            }
            mx = fmaxf(mx, __shfl_xor_sync(0xffffffffu, mx, 1));
            float mnew = fmaxf(m_r, mx);
            float scale = __expf(m_r - mnew);
            m_r = mnew;
            l_r *= scale;
            if (half == 0) scl[r] = scale;
        }
        __syncthreads();

        // ---- rescale persistent O fragments by per-row scale ----
        {
            #pragma unroll
            for (int t = 0; t < 2; t++) {
                int base = wm2 * 32 + t * 16;
                float s0 = scl[base + g4];
                float s1 = scl[base + g4 + 8];
                #pragma unroll
                for (int u = 0; u < 2; u++) {
                    oacc[t][u].x[0] *= s0; oacc[t][u].x[1] *= s0;
                    oacc[t][u].x[4] *= s0; oacc[t][u].x[5] *= s0;
                    oacc[t][u].x[2] *= s1; oacc[t][u].x[3] *= s1;
                    oacc[t][u].x[6] *= s1; oacc[t][u].x[7] *= s1;
                }
            }
        }

        float rowsum = 0.f;
        #pragma unroll
        for (int hf = 0; hf < 2; hf++) {
            // ---- pass2: exp + packed split into P ----
            {
                float* Sr = S + r * 132 + hf * 64 + half * 32;
                int pc0 = half * 32;
                #pragma unroll
                for (int c4 = 0; c4 < 32; c4 += 4) {
                    float4 sv = *(float4*)(Sr + c4);
                    float p0 = __expf(sv.x - m_r);
                    float p1 = __expf(sv.y - m_r);
                    float p2 = __expf(sv.z - m_r);
                    float p3 = __expf(sv.w - m_r);
                    rowsum += (p0 + p1) + (p2 + p3);
                    uint32_t h0, l0, h1, l1;
                    split2(p0, p1, h0, l0);
                    split2(p2, p3, h1, l1);
                    *(uint2*)(P1 + r * 72 + pc0 + c4) = make_uint2(h0, h1);
                    *(uint2*)(P2 + r * 72 + pc0 + c4) = make_uint2(l0, l1);
                }
            }
            __syncthreads();
            // ---- PV half: warp tile 32q x 32d, accumulate into persistent oacc
            #pragma unroll
            for (int kk = 0; kk < 4; kk++) {
                wmma::fragment<wmma::matrix_a, 16, 16, 16, __nv_bfloat16, wmma::row_major> a1[2], a2[2];
                #pragma unroll
                for (int t = 0; t < 2; t++) {
                    int ab = (wm2 * 32 + t * 16) * 72 + kk * 16;
                    wmma::load_matrix_sync(a1[t], P1 + ab, 72);
                    wmma::load_matrix_sync(a2[t], P2 + ab, 72);
                }
                #pragma unroll
                for (int u = 0; u < 2; u++) {
                    wmma::fragment<wmma::matrix_b, 16, 16, 16, __nv_bfloat16, wmma::row_major> b1, b2;
                    int bb = (hf * 64 + kk * 16) * 72 + wn2 * 32 + u * 16;
                    wmma::load_matrix_sync(b1, V1 + bb, 72);
                    wmma::load_matrix_sync(b2, V2 + bb, 72);
                    #pragma unroll
                    for (int t = 0; t < 2; t++) {
                        wmma::mma_sync(oacc[t][u], a1[t], b1, oacc[t][u]);
                        wmma::mma_sync(oacc[t][u], a1[t], b2, oacc[t][u]);
                        wmma::mma_sync(oacc[t][u], a2[t], b1, oacc[t][u]);
                    }
                }
            }
            __syncthreads();   // P consumed (hf) / V consumed (hf==1)
        }

        rowsum += __shfl_xor_sync(0xffffffffu, rowsum, 1);
        l_r += rowsum;
        // no O smem round-trip: next tile staging is ordered by the hf==1 sync
    }

    // epilogue: dump persistent O fragments to S, then ctx = O / l (split)
    #pragma unroll
    for (int t = 0; t < 2; t++)
        #pragma unroll
        for (int u = 0; u < 2; u++)
            wmma::store_matrix_sync(S + (wm2 * 32 + t * 16) * 132 + wn2 * 32 + u * 16,
                                    oacc[t][u], 132, wmma::mem_row_major);
    __syncthreads();
    float inv = 1.0f / l_r;
    size_t cbase = ((size_t)(b * Ss + q0 + r)) * Dd + h * DKk + half * 32;
    {
        float* Sr = S + r * 132 + half * 32;
        #pragma unroll
        for (int c4 = 0; c4 < 32; c4 += 4) {
            float v0 = Sr[c4] * inv,     v1 = Sr[c4 + 1] * inv;
            float v2 = Sr[c4 + 2] * inv, v3 = Sr[c4 + 3] * inv;
            uint32_t h0, l0, h1, l1;
            split2(v0, v1, h0, l0);
            split2(v2, v3, h1, l1);
            *(uint2*)(g_c1 + cbase + c4) = make_uint2(h0, h1);
            *(uint2*)(g_c2 + cbase + c4) = make_uint2(l0, l1);
        }
    }
}

// ==================== launch ==============================================
extern "C" void kernel_launch(void* const* d_in, const int* in_sizes, int n_in,
                              void* d_out, int out_size) {
    const float* hidden   = (const float*)d_in[0];
    const float* rms_w    = (const float*)d_in[2];
    const float* W_qkv    = (const float*)d_in[3];
    const float* W_o      = (const float*)d_in[4];
    const float* rel_bias = (const float*)d_in[5];
    float* out = (float*)d_out;

    rmsnorm_kernel<<<Bb * Ss, 256>>>(hidden, rms_w);
    bias_table_kernel<<<dim3(Ss / 256, Hh), 256>>>(rel_bias);
    tsplit_wq_kernel<<<dim3(3072 / 32, Dd / 32), 256>>>(W_qkv);
    tsplit_wo_kernel<<<dim3(Dd / 32, Dd / 32), 256>>>(W_o);

    cudaFuncSetAttribute(qkv_wmma_kernel, cudaFuncAttributeMaxDynamicSharedMemorySize, DYN_SMEM);
    qkv_wmma_kernel<<<dim3(3072 / 128, (Bb * Ss) / 128), 256, DYN_SMEM>>>();

    cudaFuncSetAttribute(attn_wmma_kernel, cudaFuncAttributeMaxDynamicSharedMemorySize, ATT_SMEM);
    attn_wmma_kernel<<<dim3(Ss / 128, Hh, Bb), 256, ATT_SMEM>>>();

    cudaFuncSetAttribute(out_wmma_kernel, cudaFuncAttributeMaxDynamicSharedMemorySize, DYN_SMEM);
    out_wmma_kernel<<<dim3(Dd / 128, (Bb * Ss) / 128), 256, DYN_SMEM>>>(hidden, out);
}

// round 15
// speedup vs baseline: 1.6091x; 1.0499x over previous
#include <cuda_runtime.h>
#include <cuda_bf16.h>
#include <mma.h>
#include <math.h>
#include <stdint.h>

using namespace nvcuda;

#define Bb 4
#define Ss 2048
#define Dd 1024
#define Hh 16
#define DKk 64
#define EPSf 1e-6f
#define NEG_BIG -3.402823466e38f

// ==================== scratch (device globals) =============================
__device__ __align__(16) float g_bias[Hh*Ss];
__device__ __align__(16) __nv_bfloat16 g_a1[Bb*Ss*Dd];    // normed hi/lo
__device__ __align__(16) __nv_bfloat16 g_a2[Bb*Ss*Dd];
__device__ __align__(16) __nv_bfloat16 g_wq1[3072*Dd];    // W_qkv^T [n][k]
__device__ __align__(16) __nv_bfloat16 g_wq2[3072*Dd];
__device__ __align__(16) __nv_bfloat16 g_wo1[Dd*Dd];      // W_o^T [n][k]
__device__ __align__(16) __nv_bfloat16 g_wo2[Dd*Dd];
__device__ __align__(16) __nv_bfloat16 g_c1[Bb*Ss*Dd];    // ctx
__device__ __align__(16) __nv_bfloat16 g_c2[Bb*Ss*Dd];
__device__ __align__(16) __nv_bfloat16 g_q1[Bb*Hh*Ss*DKk];
__device__ __align__(16) __nv_bfloat16 g_q2[Bb*Hh*Ss*DKk];
__device__ __align__(16) __nv_bfloat16 g_k1[Bb*Hh*Ss*DKk];
__device__ __align__(16) __nv_bfloat16 g_k2[Bb*Hh*Ss*DKk];
__device__ __align__(16) __nv_bfloat16 g_v1[Bb*Hh*Ss*DKk];
__device__ __align__(16) __nv_bfloat16 g_v2[Bb*Hh*Ss*DKk];

// ==================== split helper (packed pair) ===========================
__device__ __forceinline__ void split2(float va, float vb, uint32_t& hi2, uint32_t& lo2) {
    __nv_bfloat16 ha = __float2bfloat16(va);
    __nv_bfloat16 hb = __float2bfloat16(vb);
    __nv_bfloat16 la = __float2bfloat16(va - __bfloat162float(ha));
    __nv_bfloat16 lb = __float2bfloat16(vb - __bfloat162float(hb));
    hi2 = (uint32_t)__bfloat16_as_ushort(ha) | ((uint32_t)__bfloat16_as_ushort(hb) << 16);
    lo2 = (uint32_t)__bfloat16_as_ushort(la) | ((uint32_t)__bfloat16_as_ushort(lb) << 16);
}

// ==================== K0: RMSNorm -> split pairs ===========================
__global__ void __launch_bounds__(256) rmsnorm_kernel(const float* __restrict__ x,
                                                      const float* __restrict__ w) {
    int row = blockIdx.x;
    const float* xr = x + (size_t)row * Dd;
    float local = 0.f;
    for (int i = threadIdx.x; i < Dd; i += 256) { float v = xr[i]; local += v * v; }
    __shared__ float red[8];
    #pragma unroll
    for (int o = 16; o; o >>= 1) local += __shfl_xor_sync(0xffffffffu, local, o);
    if ((threadIdx.x & 31) == 0) red[threadIdx.x >> 5] = local;
    __syncthreads();
    if (threadIdx.x < 8) {
        float v = red[threadIdx.x];
        #pragma unroll
        for (int o = 4; o; o >>= 1) v += __shfl_xor_sync(0xffu, v, o);
        if (threadIdx.x == 0) red[0] = v;
    }
    __syncthreads();
    float scale = rsqrtf(red[0] * (1.0f / Dd) + EPSf);
    for (int i = threadIdx.x * 2; i < Dd; i += 512) {
        float y0 = xr[i] * scale * w[i];
        float y1 = xr[i + 1] * scale * w[i + 1];
        uint32_t hi, lo; split2(y0, y1, hi, lo);
        size_t off = (size_t)row * Dd + i;
        *(uint32_t*)(g_a1 + off) = hi;
        *(uint32_t*)(g_a2 + off) = lo;
    }
}

// ==================== K1: bias table =======================================
__global__ void bias_table_kernel(const float* __restrict__ rel_bias) {
    int d = blockIdx.x * blockDim.x + threadIdx.x;
    int h = blockIdx.y;
    if (d >= Ss) return;
    int bucket;
    if (d < 16) bucket = d;
    else {
        bucket = 16 + (int)(logf((float)d / 16.0f) / logf(8.0f) * 16.0f);
        if (bucket > 31) bucket = 31;
    }
    g_bias[h * Ss + d] = rel_bias[bucket * Hh + h];
}

// ==================== K2: weight transpose + split =========================
__device__ __forceinline__ void tsplit_body(const float* __restrict__ in,
                                            __nv_bfloat16* o1, __nv_bfloat16* o2,
                                            int K, int N) {
    __shared__ float t[32][33];
    int n0 = blockIdx.x * 32, k0 = blockIdx.y * 32;
    int tx = threadIdx.x & 31, ty = threadIdx.x >> 5;
    #pragma unroll
    for (int j = 0; j < 32; j += 8)
        t[ty + j][tx] = in[(size_t)(k0 + ty + j) * N + n0 + tx];
    __syncthreads();
    int tid = threadIdx.x;
    #pragma unroll
    for (int it = 0; it < 2; it++) {
        int p = it * 256 + tid;
        int nn = p >> 4, kp = (p & 15) * 2;
        float v0 = t[kp][nn];
        float v1 = t[kp + 1][nn];
        uint32_t hi, lo; split2(v0, v1, hi, lo);
        size_t off = (size_t)(n0 + nn) * K + k0 + kp;
        *(uint32_t*)(o1 + off) = hi;
        *(uint32_t*)(o2 + off) = lo;
    }
}
__global__ void __launch_bounds__(256) tsplit_wq_kernel(const float* __restrict__ in) {
    tsplit_body(in, g_wq1, g_wq2, Dd, 3072);
}
__global__ void __launch_bounds__(256) tsplit_wo_kernel(const float* __restrict__ in) {
    tsplit_body(in, g_wo1, g_wo2, Dd, Dd);
}

// ==================== WMMA GEMM core (pre-split inputs) ====================
#define ROWK 72
#define ARRE (128 * ROWK)
#define DYN_SMEM (4 * ARRE * 2)

typedef wmma::fragment<wmma::accumulator, 16, 16, 16, float> AccFrag;

__device__ __forceinline__ void gemm_wmma_mainloop2(
    const __nv_bfloat16* __restrict__ A1g, const __nv_bfloat16* __restrict__ A2g,
    const __nv_bfloat16* __restrict__ B1g, const __nv_bfloat16* __restrict__ B2g,
    char* dyn, AccFrag acc[4][2])
{
    int tid = threadIdx.x;
    int w = tid >> 5;
    int wm = w >> 2, wn = w & 3;
    __nv_bfloat16* sA1 = (__nv_bfloat16*)dyn;
    __nv_bfloat16* sA2 = sA1 + ARRE;
    __nv_bfloat16* sB1 = sA2 + ARRE;
    __nv_bfloat16* sB2 = sB1 + ARRE;

    for (int ch = 0; ch < Dd / 64; ch++) {
        const __nv_bfloat16* gsrc[4] = { A1g, A2g, B1g, B2g };
        __nv_bfloat16* sdst[4] = { sA1, sA2, sB1, sB2 };
        #pragma unroll
        for (int a = 0; a < 4; a++) {
            const __nv_bfloat16* g = gsrc[a] + ch * 64;
            __nv_bfloat16* s = sdst[a];
            #pragma unroll
            for (int i = 0; i < 4; i++) {
                int idx = i * 256 + tid;
                int row = idx >> 3, c8 = (idx & 7) * 8;
                *(uint4*)(s + row * ROWK + c8) =
                    *(const uint4*)(g + (size_t)row * Dd + c8);
            }
        }
        __syncthreads();
        #pragma unroll
        for (int kk = 0; kk < 4; kk++) {
            wmma::fragment<wmma::matrix_b, 16, 16, 16, __nv_bfloat16, wmma::col_major> b1[2], b2[2];
            #pragma unroll
            for (int u = 0; u < 2; u++) {
                int nb = (wn * 32 + u * 16) * ROWK + kk * 16;
                wmma::load_matrix_sync(b1[u], sB1 + nb, ROWK);
                wmma::load_matrix_sync(b2[u], sB2 + nb, ROWK);
            }
            #pragma unroll
            for (int t = 0; t < 4; t++) {
                wmma::fragment<wmma::matrix_a, 16, 16, 16, __nv_bfloat16, wmma::row_major> a1, a2;
                int ab = (wm * 64 + t * 16) * ROWK + kk * 16;
                wmma::load_matrix_sync(a1, sA1 + ab, ROWK);
                wmma::load_matrix_sync(a2, sA2 + ab, ROWK);
                #pragma unroll
                for (int u = 0; u < 2; u++) {
                    wmma::mma_sync(acc[t][u], a1, b1[u], acc[t][u]);
                    wmma::mma_sync(acc[t][u], a1, b2[u], acc[t][u]);
                    wmma::mma_sync(acc[t][u], a2, b1[u], acc[t][u]);
                }
            }
        }
        __syncthreads();
    }
}

// ---------------- QKV GEMM with split epilogue -----------------------------
__global__ void __launch_bounds__(256, 2) qkv_wmma_kernel() {
    extern __shared__ char dyn[];
    AccFrag acc[4][2];
    #pragma unroll
    for (int t = 0; t < 4; t++)
        #pragma unroll
        for (int u = 0; u < 2; u++) wmma::fill_fragment(acc[t][u], 0.0f);

    int n0 = blockIdx.x * 128, m0 = blockIdx.y * 128;
    gemm_wmma_mainloop2(g_a1 + (size_t)m0 * Dd, g_a2 + (size_t)m0 * Dd,
                        g_wq1 + (size_t)n0 * Dd, g_wq2 + (size_t)n0 * Dd, dyn, acc);

    float* ep = (float*)dyn;
    int w = threadIdx.x >> 5;
    int wm = w >> 2, wn = w & 3;
    #pragma unroll
    for (int t = 0; t < 4; t++)
        #pragma unroll
        for (int u = 0; u < 2; u++)
            wmma::store_matrix_sync(ep + (wm * 64 + t * 16) * 132 + wn * 32 + u * 16,
                                    acc[t][u], 132, wmma::mem_row_major);
    __syncthreads();

    int which = n0 >> 10;
    __nv_bfloat16* d1 = (which == 0) ? g_q1 : (which == 1) ? g_k1 : g_v1;
    __nv_bfloat16* d2 = (which == 0) ? g_q2 : (which == 1) ? g_k2 : g_v2;
    #pragma unroll
    for (int it = 0; it < 32; it++) {
        int p = it * 256 + threadIdx.x;
        int row = p >> 6, pr = p & 63;
        float a = ep[row * 132 + pr * 2];
        float b2v = ep[row * 132 + pr * 2 + 1];
        uint32_t hi, lo; split2(a, b2v, hi, lo);
        int n = n0 + pr * 2;
        int h = (n >> 6) & 15, dk0 = n & 63;
        int m = m0 + row, bb = m >> 11, s = m & 2047;
        size_t off = (((size_t)(bb * Hh + h)) * Ss + s) * DKk + dk0;
        *(uint32_t*)(d1 + off) = hi;
        *(uint32_t*)(d2 + off) = lo;
    }
}

// ---------------- out GEMM + residual --------------------------------------
__global__ void __launch_bounds__(256, 2) out_wmma_kernel(const float* __restrict__ hidden,
                                                          float* __restrict__ out) {
    extern __shared__ char dyn[];
    AccFrag acc[4][2];
    #pragma unroll
    for (int t = 0; t < 4; t++)
        #pragma unroll
        for (int u = 0; u < 2; u++) wmma::fill_fragment(acc[t][u], 0.0f);

    int n0 = blockIdx.x * 128, m0 = blockIdx.y * 128;
    gemm_wmma_mainloop2(g_c1 + (size_t)m0 * Dd, g_c2 + (size_t)m0 * Dd,
                        g_wo1 + (size_t)n0 * Dd, g_wo2 + (size_t)n0 * Dd, dyn, acc);

    int w = threadIdx.x >> 5;
    int wm = w >> 2, wn = w & 3;
    #pragma unroll
    for (int t = 0; t < 4; t++) {
        int m_sub = m0 + wm * 64 + t * 16;
        #pragma unroll
        for (int u = 0; u < 2; u++) {
            int n_sub = n0 + wn * 32 + u * 16;
            AccFrag hfrag;
            wmma::load_matrix_sync(hfrag, hidden + (size_t)m_sub * Dd + n_sub, Dd,
                                   wmma::mem_row_major);
            #pragma unroll
            for (int e = 0; e < hfrag.num_elements; e++)
                acc[t][u].x[e] += hfrag.x[e];
            wmma::store_matrix_sync(out + (size_t)m_sub * Dd + n_sub, acc[t][u], Dd,
                                    wmma::mem_row_major);
        }
    }
}

// ==================== K3: WMMA flash attention v9 ==========================
// v8 + bias/mask/row-max fused into the QK fragment epilogue (registers),
// S stored already-biased; pass1 collapses to a 4-float max. Layout verified
// in round 14: x0,x1,x4,x5 -> row g4 ; x2,x3,x6,x7 -> row g4+8;
// cols: x0,x1 -> 2tg,2tg+1 ; x4,x5 -> +8.
#define AQ1 0
#define AQ2 18432
#define AK1 36864
#define AK2 55296
#define AV1 73728
#define AV2 92160
#define AS  110592
#define AP1 178176
#define AP2 196608
#define ABI 215040
#define ASCL 216064
#define ASMX 216576
#define ATT_SMEM 218624

__global__ void __launch_bounds__(256) attn_wmma_kernel() {
    extern __shared__ char dyn[];
    __nv_bfloat16* Q1 = (__nv_bfloat16*)(dyn + AQ1);   // [128][72]
    __nv_bfloat16* Q2 = (__nv_bfloat16*)(dyn + AQ2);
    __nv_bfloat16* K1 = (__nv_bfloat16*)(dyn + AK1);   // [128][72]
    __nv_bfloat16* K2 = (__nv_bfloat16*)(dyn + AK2);
    __nv_bfloat16* V1 = (__nv_bfloat16*)(dyn + AV1);   // [128][72]
    __nv_bfloat16* V2 = (__nv_bfloat16*)(dyn + AV2);
    float* S = (float*)(dyn + AS);                     // [128][132]
    __nv_bfloat16* P1 = (__nv_bfloat16*)(dyn + AP1);   // [128][72]
    __nv_bfloat16* P2 = (__nv_bfloat16*)(dyn + AP2);
    float* bias_s = (float*)(dyn + ABI);               // [255]
    float* scl  = (float*)(dyn + ASCL);                // [128]
    float* smax = (float*)(dyn + ASMX);                // [128][4]

    int tid = threadIdx.x;
    int w = tid >> 5;
    int lane = tid & 31;
    int g4 = lane >> 2, tg = lane & 3;
    int wm = w >> 2, wn = w & 3;       // QK: 64q x 32kv
    int wm2 = w >> 1, wn2 = w & 1;     // PV: 32q x 32d
    int r = tid >> 1, half = tid & 1;
    int qb = gridDim.x - 1 - blockIdx.x;
    int q0 = qb * 128;
    int h  = blockIdx.y;
    int b  = blockIdx.z;
    size_t hoff = ((size_t)(b * Hh + h)) * Ss * DKk;
    const __nv_bfloat16* Qg1 = g_q1 + hoff;
    const __nv_bfloat16* Qg2 = g_q2 + hoff;
    const __nv_bfloat16* Kg1 = g_k1 + hoff;
    const __nv_bfloat16* Kg2 = g_k2 + hoff;
    const __nv_bfloat16* Vg1 = g_v1 + hoff;
    const __nv_bfloat16* Vg2 = g_v2 + hoff;
    const float* biasH = g_bias + h * Ss;

    #pragma unroll
    for (int i = 0; i < 4; i++) {
        int idx = i * 256 + tid;
        int row = idx >> 3, c8 = (idx & 7) * 8;
        *(uint4*)(Q1 + row * 72 + c8) = *(const uint4*)(Qg1 + (size_t)(q0 + row) * DKk + c8);
        *(uint4*)(Q2 + row * 72 + c8) = *(const uint4*)(Qg2 + (size_t)(q0 + row) * DKk + c8);
    }
    float m_r = -INFINITY, l_r = 0.f;
    AccFrag oacc[2][2];
    #pragma unroll
    for (int t = 0; t < 2; t++)
        #pragma unroll
        for (int u = 0; u < 2; u++) wmma::fill_fragment(oacc[t][u], 0.0f);
    __syncthreads();

    int ntiles = qb + 1;
    for (int kt = 0; kt < ntiles; kt++) {
        int k0 = kt * 128;
        #pragma unroll
        for (int i = 0; i < 4; i++) {
            int idx = i * 256 + tid;
            int row = idx >> 3, c8 = (idx & 7) * 8;
            size_t goff = (size_t)(k0 + row) * DKk + c8;
            int soff = row * 72 + c8;
            *(uint4*)(K1 + soff) = *(const uint4*)(Kg1 + goff);
            *(uint4*)(K2 + soff) = *(const uint4*)(Kg2 + goff);
            *(uint4*)(V1 + soff) = *(const uint4*)(Vg1 + goff);
            *(uint4*)(V2 + soff) = *(const uint4*)(Vg2 + goff);
        }
        if (tid < 255) {
            int dist = q0 - k0 - 127 + tid;
            bias_s[tid] = biasH[dist < 0 ? 0 : dist];
        }
        __syncthreads();

        // ---- QK with fused bias+mask+row-max epilogue ----
        bool diag = (k0 == q0);
        {
            AccFrag sacc[4][2];
            #pragma unroll
            for (int t = 0; t < 4; t++)
                #pragma unroll
                for (int u = 0; u < 2; u++) wmma::fill_fragment(sacc[t][u], 0.0f);
            #pragma unroll
            for (int kk = 0; kk < 4; kk++) {
                wmma::fragment<wmma::matrix_b, 16, 16, 16, __nv_bfloat16, wmma::col_major> b1[2], b2[2];
                #pragma unroll
                for (int u = 0; u < 2; u++) {
                    int bb = (wn * 32 + u * 16) * 72 + kk * 16;
                    wmma::load_matrix_sync(b1[u], K1 + bb, 72);
                    wmma::load_matrix_sync(b2[u], K2 + bb, 72);
                }
                #pragma unroll
                for (int t = 0; t < 4; t++) {
                    wmma::fragment<wmma::matrix_a, 16, 16, 16, __nv_bfloat16, wmma::row_major> a1, a2;
                    int ab = (wm * 64 + t * 16) * 72 + kk * 16;
                    wmma::load_matrix_sync(a1, Q1 + ab, 72);
                    wmma::load_matrix_sync(a2, Q2 + ab, 72);
                    #pragma unroll
                    for (int u = 0; u < 2; u++) {
                        wmma::mma_sync(sacc[t][u], a1, b1[u], sacc[t][u]);
                        wmma::mma_sync(sacc[t][u], a1, b2[u], sacc[t][u]);
                        wmma::mma_sync(sacc[t][u], a2, b1[u], sacc[t][u]);
                    }
                }
            }
            // fused epilogue: bias + mask + per-row max, then store biased S
            #pragma unroll
            for (int t = 0; t < 4; t++) {
                int row0 = wm * 64 + t * 16 + g4;
                int row1 = row0 + 8;
                float mx0 = -INFINITY, mx1 = -INFINITY;
                #pragma unroll
                for (int u = 0; u < 2; u++) {
                    float* xp = sacc[t][u].x;
                    int c0 = wn * 32 + u * 16 + 2 * tg;
                    int b00 = row0 - c0 + 127;
                    int b10 = row1 - c0 + 127;
                    xp[0] += bias_s[b00];     xp[1] += bias_s[b00 - 1];
                    xp[4] += bias_s[b00 - 8]; xp[5] += bias_s[b00 - 9];
                    xp[2] += bias_s[b10];     xp[3] += bias_s[b10 - 1];
                    xp[6] += bias_s[b10 - 8]; xp[7] += bias_s[b10 - 9];
                    if (diag) {
                        if (c0     > row0) xp[0] = NEG_BIG;
                        if (c0 + 1 > row0) xp[1] = NEG_BIG;
                        if (c0 + 8 > row0) xp[4] = NEG_BIG;
                        if (c0 + 9 > row0) xp[5] = NEG_BIG;
                        if (c0     > row1) xp[2] = NEG_BIG;
                        if (c0 + 1 > row1) xp[3] = NEG_BIG;
                        if (c0 + 8 > row1) xp[6] = NEG_BIG;
                        if (c0 + 9 > row1) xp[7] = NEG_BIG;
                    }
                    mx0 = fmaxf(mx0, fmaxf(fmaxf(xp[0], xp[1]), fmaxf(xp[4], xp[5])));
                    mx1 = fmaxf(mx1, fmaxf(fmaxf(xp[2], xp[3]), fmaxf(xp[6], xp[7])));
                }
                mx0 = fmaxf(mx0, __shfl_xor_sync(0xffffffffu, mx0, 1));
                mx0 = fmaxf(mx0, __shfl_xor_sync(0xffffffffu, mx0, 2));
                mx1 = fmaxf(mx1, __shfl_xor_sync(0xffffffffu, mx1, 1));
                mx1 = fmaxf(mx1, __shfl_xor_sync(0xffffffffu, mx1, 2));
                if (tg == 0) {
                    smax[row0 * 4 + wn] = mx0;
                    smax[row1 * 4 + wn] = mx1;
                }
                #pragma unroll
                for (int u = 0; u < 2; u++)
                    wmma::store_matrix_sync(S + (wm * 64 + t * 16) * 132 + wn * 32 + u * 16,
                                            sacc[t][u], 132, wmma::mem_row_major);
            }
        }
        __syncthreads();

        // ---- pass1-lite: combine 4 warp maxima, publish rescale ----
        {
            float mx = fmaxf(fmaxf(smax[r * 4 + 0], smax[r * 4 + 1]),
                             fmaxf(smax[r * 4 + 2], smax[r * 4 + 3]));
            float mnew = fmaxf(m_r, mx);
            float scale = __expf(m_r - mnew);
            m_r = mnew;
            l_r *= scale;
            if (half == 0) scl[r] = scale;
        }
        __syncthreads();

        // ---- rescale persistent O fragments ----
        {
            #pragma unroll
            for (int t = 0; t < 2; t++) {
                int base = wm2 * 32 + t * 16;
                float s0 = scl[base + g4];
                float s1 = scl[base + g4 + 8];
                #pragma unroll
                for (int u = 0; u < 2; u++) {
                    oacc[t][u].x[0] *= s0; oacc[t][u].x[1] *= s0;
                    oacc[t][u].x[4] *= s0; oacc[t][u].x[5] *= s0;
                    oacc[t][u].x[2] *= s1; oacc[t][u].x[3] *= s1;
                    oacc[t][u].x[6] *= s1; oacc[t][u].x[7] *= s1;
                }
            }
        }

        float rowsum = 0.f;
        #pragma unroll
        for (int hf = 0; hf < 2; hf++) {
            // ---- pass2: exp + packed split into P ----
            {
                float* Sr = S + r * 132 + hf * 64 + half * 32;
                int pc0 = half * 32;
                #pragma unroll
                for (int c4 = 0; c4 < 32; c4 += 4) {
                    float4 sv = *(float4*)(Sr + c4);
                    float p0 = __expf(sv.x - m_r);
                    float p1 = __expf(sv.y - m_r);
                    float p2 = __expf(sv.z - m_r);
                    float p3 = __expf(sv.w - m_r);
                    rowsum += (p0 + p1) + (p2 + p3);
                    uint32_t h0, l0, h1, l1;
                    split2(p0, p1, h0, l0);
                    split2(p2, p3, h1, l1);
                    *(uint2*)(P1 + r * 72 + pc0 + c4) = make_uint2(h0, h1);
                    *(uint2*)(P2 + r * 72 + pc0 + c4) = make_uint2(l0, l1);
                }
            }
            __syncthreads();
            // ---- PV half: warp tile 32q x 32d, accumulate into persistent oacc
            #pragma unroll
            for (int kk = 0; kk < 4; kk++) {
                wmma::fragment<wmma::matrix_a, 16, 16, 16, __nv_bfloat16, wmma::row_major> a1[2], a2[2];
                #pragma unroll
                for (int t = 0; t < 2; t++) {
                    int ab = (wm2 * 32 + t * 16) * 72 + kk * 16;
                    wmma::load_matrix_sync(a1[t], P1 + ab, 72);
                    wmma::load_matrix_sync(a2[t], P2 + ab, 72);
                }
                #pragma unroll
                for (int u = 0; u < 2; u++) {
                    wmma::fragment<wmma::matrix_b, 16, 16, 16, __nv_bfloat16, wmma::row_major> b1, b2;
                    int bb = (hf * 64 + kk * 16) * 72 + wn2 * 32 + u * 16;
                    wmma::load_matrix_sync(b1, V1 + bb, 72);
                    wmma::load_matrix_sync(b2, V2 + bb, 72);
                    #pragma unroll
                    for (int t = 0; t < 2; t++) {
                        wmma::mma_sync(oacc[t][u], a1[t], b1, oacc[t][u]);
                        wmma::mma_sync(oacc[t][u], a1[t], b2, oacc[t][u]);
                        wmma::mma_sync(oacc[t][u], a2[t], b1, oacc[t][u]);
                    }
                }
            }
            __syncthreads();
        }

        rowsum += __shfl_xor_sync(0xffffffffu, rowsum, 1);
        l_r += rowsum;
    }

    // epilogue: dump persistent O fragments to S, then ctx = O / l (split)
    #pragma unroll
    for (int t = 0; t < 2; t++)
        #pragma unroll
        for (int u = 0; u < 2; u++)
            wmma::store_matrix_sync(S + (wm2 * 32 + t * 16) * 132 + wn2 * 32 + u * 16,
                                    oacc[t][u], 132, wmma::mem_row_major);
    __syncthreads();
    float inv = 1.0f / l_r;
    size_t cbase = ((size_t)(b * Ss + q0 + r)) * Dd + h * DKk + half * 32;
    {
        float* Sr = S + r * 132 + half * 32;
        #pragma unroll
        for (int c4 = 0; c4 < 32; c4 += 4) {
            float v0 = Sr[c4] * inv,     v1 = Sr[c4 + 1] * inv;
            float v2 = Sr[c4 + 2] * inv, v3 = Sr[c4 + 3] * inv;
            uint32_t h0, l0, h1, l1;
            split2(v0, v1, h0, l0);
            split2(v2, v3, h1, l1);
            *(uint2*)(g_c1 + cbase + c4) = make_uint2(h0, h1);
            *(uint2*)(g_c2 + cbase + c4) = make_uint2(l0, l1);
        }
    }
}

// ==================== launch ==============================================
extern "C" void kernel_launch(void* const* d_in, const int* in_sizes, int n_in,
                              void* d_out, int out_size) {
    const float* hidden   = (const float*)d_in[0];
    const float* rms_w    = (const float*)d_in[2];
    const float* W_qkv    = (const float*)d_in[3];
    const float* W_o      = (const float*)d_in[4];
    const float* rel_bias = (const float*)d_in[5];
    float* out = (float*)d_out;

    rmsnorm_kernel<<<Bb * Ss, 256>>>(hidden, rms_w);
    bias_table_kernel<<<dim3(Ss / 256, Hh), 256>>>(rel_bias);
    tsplit_wq_kernel<<<dim3(3072 / 32, Dd / 32), 256>>>(W_qkv);
    tsplit_wo_kernel<<<dim3(Dd / 32, Dd / 32), 256>>>(W_o);

    cudaFuncSetAttribute(qkv_wmma_kernel, cudaFuncAttributeMaxDynamicSharedMemorySize, DYN_SMEM);
    qkv_wmma_kernel<<<dim3(3072 / 128, (Bb * Ss) / 128), 256, DYN_SMEM>>>();

    cudaFuncSetAttribute(attn_wmma_kernel, cudaFuncAttributeMaxDynamicSharedMemorySize, ATT_SMEM);
    attn_wmma_kernel<<<dim3(Ss / 128, Hh, Bb), 256, ATT_SMEM>>>();

    cudaFuncSetAttribute(out_wmma_kernel, cudaFuncAttributeMaxDynamicSharedMemorySize, DYN_SMEM);
    out_wmma_kernel<<<dim3(Dd / 128, (Bb * Ss) / 128), 256, DYN_SMEM>>>(hidden, out);
}

// round 16
// speedup vs baseline: 1.7013x; 1.0573x over previous
#include <cuda_runtime.h>
#include <cuda_bf16.h>
#include <mma.h>
#include <math.h>
#include <stdint.h>

using namespace nvcuda;

#define Bb 4
#define Ss 2048
#define Dd 1024
#define Hh 16
#define DKk 64
#define EPSf 1e-6f
#define NEG_BIG -3.402823466e38f

// ==================== scratch (device globals) =============================
__device__ __align__(16) float g_bias[Hh*Ss];
__device__ __align__(16) __nv_bfloat16 g_a1[Bb*Ss*Dd];    // normed hi/lo
__device__ __align__(16) __nv_bfloat16 g_a2[Bb*Ss*Dd];
__device__ __align__(16) __nv_bfloat16 g_wq1[3072*Dd];    // W_qkv^T [n][k]
__device__ __align__(16) __nv_bfloat16 g_wq2[3072*Dd];
__device__ __align__(16) __nv_bfloat16 g_wo1[Dd*Dd];      // W_o^T [n][k]
__device__ __align__(16) __nv_bfloat16 g_wo2[Dd*Dd];
__device__ __align__(16) __nv_bfloat16 g_c1[Bb*Ss*Dd];    // ctx
__device__ __align__(16) __nv_bfloat16 g_c2[Bb*Ss*Dd];
__device__ __align__(16) __nv_bfloat16 g_q1[Bb*Hh*Ss*DKk];
__device__ __align__(16) __nv_bfloat16 g_q2[Bb*Hh*Ss*DKk];
__device__ __align__(16) __nv_bfloat16 g_k1[Bb*Hh*Ss*DKk];
__device__ __align__(16) __nv_bfloat16 g_k2[Bb*Hh*Ss*DKk];
__device__ __align__(16) __nv_bfloat16 g_v1[Bb*Hh*Ss*DKk];
__device__ __align__(16) __nv_bfloat16 g_v2[Bb*Hh*Ss*DKk];

// ==================== split helper (packed pair) ===========================
__device__ __forceinline__ void split2(float va, float vb, uint32_t& hi2, uint32_t& lo2) {
    __nv_bfloat16 ha = __float2bfloat16(va);
    __nv_bfloat16 hb = __float2bfloat16(vb);
    __nv_bfloat16 la = __float2bfloat16(va - __bfloat162float(ha));
    __nv_bfloat16 lb = __float2bfloat16(vb - __bfloat162float(hb));
    hi2 = (uint32_t)__bfloat16_as_ushort(ha) | ((uint32_t)__bfloat16_as_ushort(hb) << 16);
    lo2 = (uint32_t)__bfloat16_as_ushort(la) | ((uint32_t)__bfloat16_as_ushort(lb) << 16);
}

// ==================== K0: RMSNorm -> split pairs ===========================
__global__ void __launch_bounds__(256) rmsnorm_kernel(const float* __restrict__ x,
                                                      const float* __restrict__ w) {
    int row = blockIdx.x;
    const float* xr = x + (size_t)row * Dd;
    float local = 0.f;
    for (int i = threadIdx.x; i < Dd; i += 256) { float v = xr[i]; local += v * v; }
    __shared__ float red[8];
    #pragma unroll
    for (int o = 16; o; o >>= 1) local += __shfl_xor_sync(0xffffffffu, local, o);
    if ((threadIdx.x & 31) == 0) red[threadIdx.x >> 5] = local;
    __syncthreads();
    if (threadIdx.x < 8) {
        float v = red[threadIdx.x];
        #pragma unroll
        for (int o = 4; o; o >>= 1) v += __shfl_xor_sync(0xffu, v, o);
        if (threadIdx.x == 0) red[0] = v;
    }
    __syncthreads();
    float scale = rsqrtf(red[0] * (1.0f / Dd) + EPSf);
    for (int i = threadIdx.x * 2; i < Dd; i += 512) {
        float y0 = xr[i] * scale * w[i];
        float y1 = xr[i + 1] * scale * w[i + 1];
        uint32_t hi, lo; split2(y0, y1, hi, lo);
        size_t off = (size_t)row * Dd + i;
        *(uint32_t*)(g_a1 + off) = hi;
        *(uint32_t*)(g_a2 + off) = lo;
    }
}

// ==================== K1: bias table =======================================
__global__ void bias_table_kernel(const float* __restrict__ rel_bias) {
    int d = blockIdx.x * blockDim.x + threadIdx.x;
    int h = blockIdx.y;
    if (d >= Ss) return;
    int bucket;
    if (d < 16) bucket = d;
    else {
        bucket = 16 + (int)(logf((float)d / 16.0f) / logf(8.0f) * 16.0f);
        if (bucket > 31) bucket = 31;
    }
    g_bias[h * Ss + d] = rel_bias[bucket * Hh + h];
}

// ==================== K2: weight transpose + split =========================
__device__ __forceinline__ void tsplit_body(const float* __restrict__ in,
                                            __nv_bfloat16* o1, __nv_bfloat16* o2,
                                            int K, int N) {
    __shared__ float t[32][33];
    int n0 = blockIdx.x * 32, k0 = blockIdx.y * 32;
    int tx = threadIdx.x & 31, ty = threadIdx.x >> 5;
    #pragma unroll
    for (int j = 0; j < 32; j += 8)
        t[ty + j][tx] = in[(size_t)(k0 + ty + j) * N + n0 + tx];
    __syncthreads();
    int tid = threadIdx.x;
    #pragma unroll
    for (int it = 0; it < 2; it++) {
        int p = it * 256 + tid;
        int nn = p >> 4, kp = (p & 15) * 2;
        float v0 = t[kp][nn];
        float v1 = t[kp + 1][nn];
        uint32_t hi, lo; split2(v0, v1, hi, lo);
        size_t off = (size_t)(n0 + nn) * K + k0 + kp;
        *(uint32_t*)(o1 + off) = hi;
        *(uint32_t*)(o2 + off) = lo;
    }
}
__global__ void __launch_bounds__(256) tsplit_wq_kernel(const float* __restrict__ in) {
    tsplit_body(in, g_wq1, g_wq2, Dd, 3072);
}
__global__ void __launch_bounds__(256) tsplit_wo_kernel(const float* __restrict__ in) {
    tsplit_body(in, g_wo1, g_wo2, Dd, Dd);
}

// ==================== WMMA GEMM core (pre-split inputs) ====================
#define ROWK 72
#define ARRE (128 * ROWK)
#define DYN_SMEM (4 * ARRE * 2)

typedef wmma::fragment<wmma::accumulator, 16, 16, 16, float> AccFrag;

__device__ __forceinline__ void gemm_wmma_mainloop2(
    const __nv_bfloat16* __restrict__ A1g, const __nv_bfloat16* __restrict__ A2g,
    const __nv_bfloat16* __restrict__ B1g, const __nv_bfloat16* __restrict__ B2g,
    char* dyn, AccFrag acc[4][2])
{
    int tid = threadIdx.x;
    int w = tid >> 5;
    int wm = w >> 2, wn = w & 3;
    __nv_bfloat16* sA1 = (__nv_bfloat16*)dyn;
    __nv_bfloat16* sA2 = sA1 + ARRE;
    __nv_bfloat16* sB1 = sA2 + ARRE;
    __nv_bfloat16* sB2 = sB1 + ARRE;

    for (int ch = 0; ch < Dd / 64; ch++) {
        const __nv_bfloat16* gsrc[4] = { A1g, A2g, B1g, B2g };
        __nv_bfloat16* sdst[4] = { sA1, sA2, sB1, sB2 };
        #pragma unroll
        for (int a = 0; a < 4; a++) {
            const __nv_bfloat16* g = gsrc[a] + ch * 64;
            __nv_bfloat16* s = sdst[a];
            #pragma unroll
            for (int i = 0; i < 4; i++) {
                int idx = i * 256 + tid;
                int row = idx >> 3, c8 = (idx & 7) * 8;
                *(uint4*)(s + row * ROWK + c8) =
                    *(const uint4*)(g + (size_t)row * Dd + c8);
            }
        }
        __syncthreads();
        #pragma unroll
        for (int kk = 0; kk < 4; kk++) {
            wmma::fragment<wmma::matrix_b, 16, 16, 16, __nv_bfloat16, wmma::col_major> b1[2], b2[2];
            #pragma unroll
            for (int u = 0; u < 2; u++) {
                int nb = (wn * 32 + u * 16) * ROWK + kk * 16;
                wmma::load_matrix_sync(b1[u], sB1 + nb, ROWK);
                wmma::load_matrix_sync(b2[u], sB2 + nb, ROWK);
            }
            #pragma unroll
            for (int t = 0; t < 4; t++) {
                wmma::fragment<wmma::matrix_a, 16, 16, 16, __nv_bfloat16, wmma::row_major> a1, a2;
                int ab = (wm * 64 + t * 16) * ROWK + kk * 16;
                wmma::load_matrix_sync(a1, sA1 + ab, ROWK);
                wmma::load_matrix_sync(a2, sA2 + ab, ROWK);
                #pragma unroll
                for (int u = 0; u < 2; u++) {
                    wmma::mma_sync(acc[t][u], a1, b1[u], acc[t][u]);
                    wmma::mma_sync(acc[t][u], a1, b2[u], acc[t][u]);
                    wmma::mma_sync(acc[t][u], a2, b1[u], acc[t][u]);
                }
            }
        }
        __syncthreads();
    }
}

// ---------------- QKV GEMM with split epilogue -----------------------------
__global__ void __launch_bounds__(256, 2) qkv_wmma_kernel() {
    extern __shared__ char dyn[];
    AccFrag acc[4][2];
    #pragma unroll
    for (int t = 0; t < 4; t++)
        #pragma unroll
        for (int u = 0; u < 2; u++) wmma::fill_fragment(acc[t][u], 0.0f);

    int n0 = blockIdx.x * 128, m0 = blockIdx.y * 128;
    gemm_wmma_mainloop2(g_a1 + (size_t)m0 * Dd, g_a2 + (size_t)m0 * Dd,
                        g_wq1 + (size_t)n0 * Dd, g_wq2 + (size_t)n0 * Dd, dyn, acc);

    float* ep = (float*)dyn;
    int w = threadIdx.x >> 5;
    int wm = w >> 2, wn = w & 3;
    #pragma unroll
    for (int t = 0; t < 4; t++)
        #pragma unroll
        for (int u = 0; u < 2; u++)
            wmma::store_matrix_sync(ep + (wm * 64 + t * 16) * 132 + wn * 32 + u * 16,
                                    acc[t][u], 132, wmma::mem_row_major);
    __syncthreads();

    int which = n0 >> 10;
    __nv_bfloat16* d1 = (which == 0) ? g_q1 : (which == 1) ? g_k1 : g_v1;
    __nv_bfloat16* d2 = (which == 0) ? g_q2 : (which == 1) ? g_k2 : g_v2;
    #pragma unroll
    for (int it = 0; it < 32; it++) {
        int p = it * 256 + threadIdx.x;
        int row = p >> 6, pr = p & 63;
        float a = ep[row * 132 + pr * 2];
        float b2v = ep[row * 132 + pr * 2 + 1];
        uint32_t hi, lo; split2(a, b2v, hi, lo);
        int n = n0 + pr * 2;
        int h = (n >> 6) & 15, dk0 = n & 63;
        int m = m0 + row, bb = m >> 11, s = m & 2047;
        size_t off = (((size_t)(bb * Hh + h)) * Ss + s) * DKk + dk0;
        *(uint32_t*)(d1 + off) = hi;
        *(uint32_t*)(d2 + off) = lo;
    }
}

// ---------------- out GEMM + residual --------------------------------------
__global__ void __launch_bounds__(256, 2) out_wmma_kernel(const float* __restrict__ hidden,
                                                          float* __restrict__ out) {
    extern __shared__ char dyn[];
    AccFrag acc[4][2];
    #pragma unroll
    for (int t = 0; t < 4; t++)
        #pragma unroll
        for (int u = 0; u < 2; u++) wmma::fill_fragment(acc[t][u], 0.0f);

    int n0 = blockIdx.x * 128, m0 = blockIdx.y * 128;
    gemm_wmma_mainloop2(g_c1 + (size_t)m0 * Dd, g_c2 + (size_t)m0 * Dd,
                        g_wo1 + (size_t)n0 * Dd, g_wo2 + (size_t)n0 * Dd, dyn, acc);

    int w = threadIdx.x >> 5;
    int wm = w >> 2, wn = w & 3;
    #pragma unroll
    for (int t = 0; t < 4; t++) {
        int m_sub = m0 + wm * 64 + t * 16;
        #pragma unroll
        for (int u = 0; u < 2; u++) {
            int n_sub = n0 + wn * 32 + u * 16;
            AccFrag hfrag;
            wmma::load_matrix_sync(hfrag, hidden + (size_t)m_sub * Dd + n_sub, Dd,
                                   wmma::mem_row_major);
            #pragma unroll
            for (int e = 0; e < hfrag.num_elements; e++)
                acc[t][u].x[e] += hfrag.x[e];
            wmma::store_matrix_sync(out + (size_t)m_sub * Dd + n_sub, acc[t][u], Dd,
                                    wmma::mem_row_major);
        }
    }
}

// ==================== K3: WMMA flash attention v10 =========================
// Fully fragment-resident softmax: QK sacc stays in registers through
// bias/mask/max AND exp; P written split directly from fragments; the S tile
// is gone from the mainloop. PV consumes full 128-kv P in one pass.
#define PROW 136
#define AQ1 0
#define AQ2 18432
#define AK1 36864
#define AK2 55296
#define AV1 73728
#define AV2 92160
#define AP1 110592
#define AP2 145408
#define ABI 180224
#define ASCL 181248
#define AMR  181760
#define ASMX 182272
#define ASUM 184320
#define ATT_SMEM 186368

__global__ void __launch_bounds__(256) attn_wmma_kernel() {
    extern __shared__ char dyn[];
    __nv_bfloat16* Q1 = (__nv_bfloat16*)(dyn + AQ1);   // [128][72]
    __nv_bfloat16* Q2 = (__nv_bfloat16*)(dyn + AQ2);
    __nv_bfloat16* K1 = (__nv_bfloat16*)(dyn + AK1);   // [128][72]
    __nv_bfloat16* K2 = (__nv_bfloat16*)(dyn + AK2);
    __nv_bfloat16* V1 = (__nv_bfloat16*)(dyn + AV1);   // [128][72]
    __nv_bfloat16* V2 = (__nv_bfloat16*)(dyn + AV2);
    __nv_bfloat16* P1 = (__nv_bfloat16*)(dyn + AP1);   // [128][136] full width
    __nv_bfloat16* P2 = (__nv_bfloat16*)(dyn + AP2);
    float* bias_s = (float*)(dyn + ABI);               // [255]
    float* scl  = (float*)(dyn + ASCL);                // [128]
    float* mrow_s = (float*)(dyn + AMR);               // [128]
    float* smax = (float*)(dyn + ASMX);                // [128][4]
    float* ssum = (float*)(dyn + ASUM);                // [128][4]

    int tid = threadIdx.x;
    int w = tid >> 5;
    int lane = tid & 31;
    int g4 = lane >> 2, tg = lane & 3;
    int wm = w >> 2, wn = w & 3;       // QK: 64q x 32kv
    int wm2 = w >> 1, wn2 = w & 1;     // PV: 32q x 32d
    int r = tid >> 1, half = tid & 1;
    int qb = gridDim.x - 1 - blockIdx.x;
    int q0 = qb * 128;
    int h  = blockIdx.y;
    int b  = blockIdx.z;
    size_t hoff = ((size_t)(b * Hh + h)) * Ss * DKk;
    const __nv_bfloat16* Qg1 = g_q1 + hoff;
    const __nv_bfloat16* Qg2 = g_q2 + hoff;
    const __nv_bfloat16* Kg1 = g_k1 + hoff;
    const __nv_bfloat16* Kg2 = g_k2 + hoff;
    const __nv_bfloat16* Vg1 = g_v1 + hoff;
    const __nv_bfloat16* Vg2 = g_v2 + hoff;
    const float* biasH = g_bias + h * Ss;

    #pragma unroll
    for (int i = 0; i < 4; i++) {
        int idx = i * 256 + tid;
        int row = idx >> 3, c8 = (idx & 7) * 8;
        *(uint4*)(Q1 + row * 72 + c8) = *(const uint4*)(Qg1 + (size_t)(q0 + row) * DKk + c8);
        *(uint4*)(Q2 + row * 72 + c8) = *(const uint4*)(Qg2 + (size_t)(q0 + row) * DKk + c8);
    }
    float m_r = -INFINITY, l_r = 0.f;
    AccFrag oacc[2][2];
    #pragma unroll
    for (int t = 0; t < 2; t++)
        #pragma unroll
        for (int u = 0; u < 2; u++) wmma::fill_fragment(oacc[t][u], 0.0f);
    __syncthreads();

    int ntiles = qb + 1;
    for (int kt = 0; kt < ntiles; kt++) {
        int k0 = kt * 128;
        #pragma unroll
        for (int i = 0; i < 4; i++) {
            int idx = i * 256 + tid;
            int row = idx >> 3, c8 = (idx & 7) * 8;
            size_t goff = (size_t)(k0 + row) * DKk + c8;
            int soff = row * 72 + c8;
            *(uint4*)(K1 + soff) = *(const uint4*)(Kg1 + goff);
            *(uint4*)(K2 + soff) = *(const uint4*)(Kg2 + goff);
            *(uint4*)(V1 + soff) = *(const uint4*)(Vg1 + goff);
            *(uint4*)(V2 + soff) = *(const uint4*)(Vg2 + goff);
        }
        if (tid < 255) {
            int dist = q0 - k0 - 127 + tid;
            bias_s[tid] = biasH[dist < 0 ? 0 : dist];
        }
        __syncthreads();

        // ---- QK with fused bias+mask+row-max (sacc stays in registers) ----
        bool diag = (k0 == q0);
        AccFrag sacc[4][2];
        {
            #pragma unroll
            for (int t = 0; t < 4; t++)
                #pragma unroll
                for (int u = 0; u < 2; u++) wmma::fill_fragment(sacc[t][u], 0.0f);
            #pragma unroll
            for (int kk = 0; kk < 4; kk++) {
                wmma::fragment<wmma::matrix_b, 16, 16, 16, __nv_bfloat16, wmma::col_major> b1[2], b2[2];
                #pragma unroll
                for (int u = 0; u < 2; u++) {
                    int bb = (wn * 32 + u * 16) * 72 + kk * 16;
                    wmma::load_matrix_sync(b1[u], K1 + bb, 72);
                    wmma::load_matrix_sync(b2[u], K2 + bb, 72);
                }
                #pragma unroll
                for (int t = 0; t < 4; t++) {
                    wmma::fragment<wmma::matrix_a, 16, 16, 16, __nv_bfloat16, wmma::row_major> a1, a2;
                    int ab = (wm * 64 + t * 16) * 72 + kk * 16;
                    wmma::load_matrix_sync(a1, Q1 + ab, 72);
                    wmma::load_matrix_sync(a2, Q2 + ab, 72);
                    #pragma unroll
                    for (int u = 0; u < 2; u++) {
                        wmma::mma_sync(sacc[t][u], a1, b1[u], sacc[t][u]);
                        wmma::mma_sync(sacc[t][u], a1, b2[u], sacc[t][u]);
                        wmma::mma_sync(sacc[t][u], a2, b1[u], sacc[t][u]);
                    }
                }
            }
            #pragma unroll
            for (int t = 0; t < 4; t++) {
                int row0 = wm * 64 + t * 16 + g4;
                int row1 = row0 + 8;
                float mx0 = -INFINITY, mx1 = -INFINITY;
                #pragma unroll
                for (int u = 0; u < 2; u++) {
                    float* xp = sacc[t][u].x;
                    int c0 = wn * 32 + u * 16 + 2 * tg;
                    int b00 = row0 - c0 + 127;
                    int b10 = row1 - c0 + 127;
                    xp[0] += bias_s[b00];     xp[1] += bias_s[b00 - 1];
                    xp[4] += bias_s[b00 - 8]; xp[5] += bias_s[b00 - 9];
                    xp[2] += bias_s[b10];     xp[3] += bias_s[b10 - 1];
                    xp[6] += bias_s[b10 - 8]; xp[7] += bias_s[b10 - 9];
                    if (diag) {
                        if (c0     > row0) xp[0] = NEG_BIG;
                        if (c0 + 1 > row0) xp[1] = NEG_BIG;
                        if (c0 + 8 > row0) xp[4] = NEG_BIG;
                        if (c0 + 9 > row0) xp[5] = NEG_BIG;
                        if (c0     > row1) xp[2] = NEG_BIG;
                        if (c0 + 1 > row1) xp[3] = NEG_BIG;
                        if (c0 + 8 > row1) xp[6] = NEG_BIG;
                        if (c0 + 9 > row1) xp[7] = NEG_BIG;
                    }
                    mx0 = fmaxf(mx0, fmaxf(fmaxf(xp[0], xp[1]), fmaxf(xp[4], xp[5])));
                    mx1 = fmaxf(mx1, fmaxf(fmaxf(xp[2], xp[3]), fmaxf(xp[6], xp[7])));
                }
                mx0 = fmaxf(mx0, __shfl_xor_sync(0xffffffffu, mx0, 1));
                mx0 = fmaxf(mx0, __shfl_xor_sync(0xffffffffu, mx0, 2));
                mx1 = fmaxf(mx1, __shfl_xor_sync(0xffffffffu, mx1, 1));
                mx1 = fmaxf(mx1, __shfl_xor_sync(0xffffffffu, mx1, 2));
                if (tg == 0) {
                    smax[row0 * 4 + wn] = mx0;
                    smax[row1 * 4 + wn] = mx1;
                }
            }
        }
        __syncthreads();

        // ---- pass1-lite: combine maxima, publish rescale + mrow ----
        {
            float mx = fmaxf(fmaxf(smax[r * 4 + 0], smax[r * 4 + 1]),
                             fmaxf(smax[r * 4 + 2], smax[r * 4 + 3]));
            float mnew = fmaxf(m_r, mx);
            float scale = __expf(m_r - mnew);
            m_r = mnew;
            l_r *= scale;
            if (half == 0) { scl[r] = scale; mrow_s[r] = mnew; }
        }
        __syncthreads();

        // ---- rescale persistent O fragments ----
        #pragma unroll
        for (int t = 0; t < 2; t++) {
            int base = wm2 * 32 + t * 16;
            float s0 = scl[base + g4];
            float s1 = scl[base + g4 + 8];
            #pragma unroll
            for (int u = 0; u < 2; u++) {
                oacc[t][u].x[0] *= s0; oacc[t][u].x[1] *= s0;
                oacc[t][u].x[4] *= s0; oacc[t][u].x[5] *= s0;
                oacc[t][u].x[2] *= s1; oacc[t][u].x[3] *= s1;
                oacc[t][u].x[6] *= s1; oacc[t][u].x[7] *= s1;
            }
        }

        // ---- exp in fragments, split-store P directly, partial rowsums ----
        #pragma unroll
        for (int t = 0; t < 4; t++) {
            int row0 = wm * 64 + t * 16 + g4;
            int row1 = row0 + 8;
            float m0 = mrow_s[row0];
            float m1 = mrow_s[row1];
            float rs0 = 0.f, rs1 = 0.f;
            #pragma unroll
            for (int u = 0; u < 2; u++) {
                float* xp = sacc[t][u].x;
                int c0 = wn * 32 + u * 16 + 2 * tg;
                float p0 = __expf(xp[0] - m0), p1 = __expf(xp[1] - m0);
                float p4 = __expf(xp[4] - m0), p5 = __expf(xp[5] - m0);
                float p2 = __expf(xp[2] - m1), p3 = __expf(xp[3] - m1);
                float p6 = __expf(xp[6] - m1), p7 = __expf(xp[7] - m1);
                rs0 += (p0 + p1) + (p4 + p5);
                rs1 += (p2 + p3) + (p6 + p7);
                uint32_t hi, lo;
                split2(p0, p1, hi, lo);
                *(uint32_t*)(P1 + row0 * PROW + c0) = hi;
                *(uint32_t*)(P2 + row0 * PROW + c0) = lo;
                split2(p4, p5, hi, lo);
                *(uint32_t*)(P1 + row0 * PROW + c0 + 8) = hi;
                *(uint32_t*)(P2 + row0 * PROW + c0 + 8) = lo;
                split2(p2, p3, hi, lo);
                *(uint32_t*)(P1 + row1 * PROW + c0) = hi;
                *(uint32_t*)(P2 + row1 * PROW + c0) = lo;
                split2(p6, p7, hi, lo);
                *(uint32_t*)(P1 + row1 * PROW + c0 + 8) = hi;
                *(uint32_t*)(P2 + row1 * PROW + c0 + 8) = lo;
            }
            rs0 += __shfl_xor_sync(0xffffffffu, rs0, 1);
            rs0 += __shfl_xor_sync(0xffffffffu, rs0, 2);
            rs1 += __shfl_xor_sync(0xffffffffu, rs1, 1);
            rs1 += __shfl_xor_sync(0xffffffffu, rs1, 2);
            if (tg == 0) {
                ssum[row0 * 4 + wn] = rs0;
                ssum[row1 * 4 + wn] = rs1;
            }
        }
        __syncthreads();

        // ---- l update + PV over full 128-kv P ----
        l_r += (ssum[r * 4 + 0] + ssum[r * 4 + 1]) + (ssum[r * 4 + 2] + ssum[r * 4 + 3]);
        #pragma unroll
        for (int kk = 0; kk < 8; kk++) {
            wmma::fragment<wmma::matrix_a, 16, 16, 16, __nv_bfloat16, wmma::row_major> a1[2], a2[2];
            #pragma unroll
            for (int t = 0; t < 2; t++) {
                int ab = (wm2 * 32 + t * 16) * PROW + kk * 16;
                wmma::load_matrix_sync(a1[t], P1 + ab, PROW);
                wmma::load_matrix_sync(a2[t], P2 + ab, PROW);
            }
            #pragma unroll
            for (int u = 0; u < 2; u++) {
                wmma::fragment<wmma::matrix_b, 16, 16, 16, __nv_bfloat16, wmma::row_major> b1, b2;
                int bb = (kk * 16) * 72 + wn2 * 32 + u * 16;
                wmma::load_matrix_sync(b1, V1 + bb, 72);
                wmma::load_matrix_sync(b2, V2 + bb, 72);
                #pragma unroll
                for (int t = 0; t < 2; t++) {
                    wmma::mma_sync(oacc[t][u], a1[t], b1, oacc[t][u]);
                    wmma::mma_sync(oacc[t][u], a1[t], b2, oacc[t][u]);
                    wmma::mma_sync(oacc[t][u], a2[t], b1, oacc[t][u]);
                }
            }
        }
        __syncthreads();   // P/V consumed before next tile staging
    }

    // epilogue: dump O fragments into P area (reused as float ep[128][132])
    float* ep = (float*)(dyn + AP1);
    #pragma unroll
    for (int t = 0; t < 2; t++)
        #pragma unroll
        for (int u = 0; u < 2; u++)
            wmma::store_matrix_sync(ep + (wm2 * 32 + t * 16) * 132 + wn2 * 32 + u * 16,
                                    oacc[t][u], 132, wmma::mem_row_major);
    __syncthreads();
    float inv = 1.0f / l_r;
    size_t cbase = ((size_t)(b * Ss + q0 + r)) * Dd + h * DKk + half * 32;
    {
        float* Sr = ep + r * 132 + half * 32;
        #pragma unroll
        for (int c4 = 0; c4 < 32; c4 += 4) {
            float v0 = Sr[c4] * inv,     v1 = Sr[c4 + 1] * inv;
            float v2 = Sr[c4 + 2] * inv, v3 = Sr[c4 + 3] * inv;
            uint32_t h0, l0, h1, l1;
            split2(v0, v1, h0, l0);
            split2(v2, v3, h1, l1);
            *(uint2*)(g_c1 + cbase + c4) = make_uint2(h0, h1);
            *(uint2*)(g_c2 + cbase + c4) = make_uint2(l0, l1);
        }
    }
}

// ==================== launch ==============================================
extern "C" void kernel_launch(void* const* d_in, const int* in_sizes, int n_in,
                              void* d_out, int out_size) {
    const float* hidden   = (const float*)d_in[0];
    const float* rms_w    = (const float*)d_in[2];
    const float* W_qkv    = (const float*)d_in[3];
    const float* W_o      = (const float*)d_in[4];
    const float* rel_bias = (const float*)d_in[5];
    float* out = (float*)d_out;

    rmsnorm_kernel<<<Bb * Ss, 256>>>(hidden, rms_w);
    bias_table_kernel<<<dim3(Ss / 256, Hh), 256>>>(rel_bias);
    tsplit_wq_kernel<<<dim3(3072 / 32, Dd / 32), 256>>>(W_qkv);
    tsplit_wo_kernel<<<dim3(Dd / 32, Dd / 32), 256>>>(W_o);

    cudaFuncSetAttribute(qkv_wmma_kernel, cudaFuncAttributeMaxDynamicSharedMemorySize, DYN_SMEM);
    qkv_wmma_kernel<<<dim3(3072 / 128, (Bb * Ss) / 128), 256, DYN_SMEM>>>();

    cudaFuncSetAttribute(attn_wmma_kernel, cudaFuncAttributeMaxDynamicSharedMemorySize, ATT_SMEM);
    attn_wmma_kernel<<<dim3(Ss / 128, Hh, Bb), 256, ATT_SMEM>>>();

    cudaFuncSetAttribute(out_wmma_kernel, cudaFuncAttributeMaxDynamicSharedMemorySize, DYN_SMEM);
    out_wmma_kernel<<<dim3(Dd / 128, (Bb * Ss) / 128), 256, DYN_SMEM>>>(hidden, out);
}

// round 17
// speedup vs baseline: 1.7434x; 1.0247x over previous
#include <cuda_runtime.h>
#include <cuda_bf16.h>
#include <mma.h>
#include <math.h>
#include <stdint.h>

using namespace nvcuda;

#define Bb 4
#define Ss 2048
#define Dd 1024
#define Hh 16
#define DKk 64
#define EPSf 1e-6f
#define NEG_BIG -3.402823466e38f

// ==================== scratch (device globals) =============================
__device__ __align__(16) float g_bias[Hh*Ss];
__device__ __align__(16) __nv_bfloat16 g_a1[Bb*Ss*Dd];    // normed hi/lo
__device__ __align__(16) __nv_bfloat16 g_a2[Bb*Ss*Dd];
__device__ __align__(16) __nv_bfloat16 g_wq1[3072*Dd];    // W_qkv^T [n][k]
__device__ __align__(16) __nv_bfloat16 g_wq2[3072*Dd];
__device__ __align__(16) __nv_bfloat16 g_wo1[Dd*Dd];      // W_o^T [n][k]
__device__ __align__(16) __nv_bfloat16 g_wo2[Dd*Dd];
__device__ __align__(16) __nv_bfloat16 g_c1[Bb*Ss*Dd];    // ctx
__device__ __align__(16) __nv_bfloat16 g_c2[Bb*Ss*Dd];
__device__ __align__(16) __nv_bfloat16 g_q1[Bb*Hh*Ss*DKk];
__device__ __align__(16) __nv_bfloat16 g_q2[Bb*Hh*Ss*DKk];
__device__ __align__(16) __nv_bfloat16 g_k1[Bb*Hh*Ss*DKk];
__device__ __align__(16) __nv_bfloat16 g_k2[Bb*Hh*Ss*DKk];
__device__ __align__(16) __nv_bfloat16 g_v1[Bb*Hh*Ss*DKk];
__device__ __align__(16) __nv_bfloat16 g_v2[Bb*Hh*Ss*DKk];

// ==================== split helper (packed pair) ===========================
__device__ __forceinline__ void split2(float va, float vb, uint32_t& hi2, uint32_t& lo2) {
    __nv_bfloat16 ha = __float2bfloat16(va);
    __nv_bfloat16 hb = __float2bfloat16(vb);
    __nv_bfloat16 la = __float2bfloat16(va - __bfloat162float(ha));
    __nv_bfloat16 lb = __float2bfloat16(vb - __bfloat162float(hb));
    hi2 = (uint32_t)__bfloat16_as_ushort(ha) | ((uint32_t)__bfloat16_as_ushort(hb) << 16);
    lo2 = (uint32_t)__bfloat16_as_ushort(la) | ((uint32_t)__bfloat16_as_ushort(lb) << 16);
}

// ==================== K0: RMSNorm -> split pairs ===========================
__global__ void __launch_bounds__(256) rmsnorm_kernel(const float* __restrict__ x,
                                                      const float* __restrict__ w) {
    int row = blockIdx.x;
    const float* xr = x + (size_t)row * Dd;
    float local = 0.f;
    for (int i = threadIdx.x; i < Dd; i += 256) { float v = xr[i]; local += v * v; }
    __shared__ float red[8];
    #pragma unroll
    for (int o = 16; o; o >>= 1) local += __shfl_xor_sync(0xffffffffu, local, o);
    if ((threadIdx.x & 31) == 0) red[threadIdx.x >> 5] = local;
    __syncthreads();
    if (threadIdx.x < 8) {
        float v = red[threadIdx.x];
        #pragma unroll
        for (int o = 4; o; o >>= 1) v += __shfl_xor_sync(0xffu, v, o);
        if (threadIdx.x == 0) red[0] = v;
    }
    __syncthreads();
    float scale = rsqrtf(red[0] * (1.0f / Dd) + EPSf);
    for (int i = threadIdx.x * 2; i < Dd; i += 512) {
        float y0 = xr[i] * scale * w[i];
        float y1 = xr[i + 1] * scale * w[i + 1];
        uint32_t hi, lo; split2(y0, y1, hi, lo);
        size_t off = (size_t)row * Dd + i;
        *(uint32_t*)(g_a1 + off) = hi;
        *(uint32_t*)(g_a2 + off) = lo;
    }
}

// ==================== K1: bias table =======================================
__global__ void bias_table_kernel(const float* __restrict__ rel_bias) {
    int d = blockIdx.x * blockDim.x + threadIdx.x;
    int h = blockIdx.y;
    if (d >= Ss) return;
    int bucket;
    if (d < 16) bucket = d;
    else {
        bucket = 16 + (int)(logf((float)d / 16.0f) / logf(8.0f) * 16.0f);
        if (bucket > 31) bucket = 31;
    }
    g_bias[h * Ss + d] = rel_bias[bucket * Hh + h];
}

// ==================== K2: weight transpose + split =========================
__device__ __forceinline__ void tsplit_body(const float* __restrict__ in,
                                            __nv_bfloat16* o1, __nv_bfloat16* o2,
                                            int K, int N) {
    __shared__ float t[32][33];
    int n0 = blockIdx.x * 32, k0 = blockIdx.y * 32;
    int tx = threadIdx.x & 31, ty = threadIdx.x >> 5;
    #pragma unroll
    for (int j = 0; j < 32; j += 8)
        t[ty + j][tx] = in[(size_t)(k0 + ty + j) * N + n0 + tx];
    __syncthreads();
    int tid = threadIdx.x;
    #pragma unroll
    for (int it = 0; it < 2; it++) {
        int p = it * 256 + tid;
        int nn = p >> 4, kp = (p & 15) * 2;
        float v0 = t[kp][nn];
        float v1 = t[kp + 1][nn];
        uint32_t hi, lo; split2(v0, v1, hi, lo);
        size_t off = (size_t)(n0 + nn) * K + k0 + kp;
        *(uint32_t*)(o1 + off) = hi;
        *(uint32_t*)(o2 + off) = lo;
    }
}
__global__ void __launch_bounds__(256) tsplit_wq_kernel(const float* __restrict__ in) {
    tsplit_body(in, g_wq1, g_wq2, Dd, 3072);
}
__global__ void __launch_bounds__(256) tsplit_wo_kernel(const float* __restrict__ in) {
    tsplit_body(in, g_wo1, g_wo2, Dd, Dd);
}

// ==================== WMMA GEMM core (pre-split inputs) ====================
#define ROWK 72
#define ARRE (128 * ROWK)
#define DYN_SMEM (4 * ARRE * 2)

typedef wmma::fragment<wmma::accumulator, 16, 16, 16, float> AccFrag;

__device__ __forceinline__ void gemm_wmma_mainloop2(
    const __nv_bfloat16* __restrict__ A1g, const __nv_bfloat16* __restrict__ A2g,
    const __nv_bfloat16* __restrict__ B1g, const __nv_bfloat16* __restrict__ B2g,
    char* dyn, AccFrag acc[4][2])
{
    int tid = threadIdx.x;
    int w = tid >> 5;
    int wm = w >> 2, wn = w & 3;
    __nv_bfloat16* sA1 = (__nv_bfloat16*)dyn;
    __nv_bfloat16* sA2 = sA1 + ARRE;
    __nv_bfloat16* sB1 = sA2 + ARRE;
    __nv_bfloat16* sB2 = sB1 + ARRE;

    for (int ch = 0; ch < Dd / 64; ch++) {
        const __nv_bfloat16* gsrc[4] = { A1g, A2g, B1g, B2g };
        __nv_bfloat16* sdst[4] = { sA1, sA2, sB1, sB2 };
        #pragma unroll
        for (int a = 0; a < 4; a++) {
            const __nv_bfloat16* g = gsrc[a] + ch * 64;
            __nv_bfloat16* s = sdst[a];
            #pragma unroll
            for (int i = 0; i < 4; i++) {
                int idx = i * 256 + tid;
                int row = idx >> 3, c8 = (idx & 7) * 8;
                *(uint4*)(s + row * ROWK + c8) =
                    *(const uint4*)(g + (size_t)row * Dd + c8);
            }
        }
        __syncthreads();
        #pragma unroll
        for (int kk = 0; kk < 4; kk++) {
            wmma::fragment<wmma::matrix_b, 16, 16, 16, __nv_bfloat16, wmma::col_major> b1[2], b2[2];
            #pragma unroll
            for (int u = 0; u < 2; u++) {
                int nb = (wn * 32 + u * 16) * ROWK + kk * 16;
                wmma::load_matrix_sync(b1[u], sB1 + nb, ROWK);
                wmma::load_matrix_sync(b2[u], sB2 + nb, ROWK);
            }
            #pragma unroll
            for (int t = 0; t < 4; t++) {
                wmma::fragment<wmma::matrix_a, 16, 16, 16, __nv_bfloat16, wmma::row_major> a1, a2;
                int ab = (wm * 64 + t * 16) * ROWK + kk * 16;
                wmma::load_matrix_sync(a1, sA1 + ab, ROWK);
                wmma::load_matrix_sync(a2, sA2 + ab, ROWK);
                #pragma unroll
                for (int u = 0; u < 2; u++) {
                    wmma::mma_sync(acc[t][u], a1, b1[u], acc[t][u]);
                    wmma::mma_sync(acc[t][u], a1, b2[u], acc[t][u]);
                    wmma::mma_sync(acc[t][u], a2, b1[u], acc[t][u]);
                }
            }
        }
        __syncthreads();
    }
}

// ---------------- QKV GEMM with split epilogue -----------------------------
__global__ void __launch_bounds__(256, 2) qkv_wmma_kernel() {
    extern __shared__ char dyn[];
    AccFrag acc[4][2];
    #pragma unroll
    for (int t = 0; t < 4; t++)
        #pragma unroll
        for (int u = 0; u < 2; u++) wmma::fill_fragment(acc[t][u], 0.0f);

    int n0 = blockIdx.x * 128, m0 = blockIdx.y * 128;
    gemm_wmma_mainloop2(g_a1 + (size_t)m0 * Dd, g_a2 + (size_t)m0 * Dd,
                        g_wq1 + (size_t)n0 * Dd, g_wq2 + (size_t)n0 * Dd, dyn, acc);

    float* ep = (float*)dyn;
    int w = threadIdx.x >> 5;
    int wm = w >> 2, wn = w & 3;
    #pragma unroll
    for (int t = 0; t < 4; t++)
        #pragma unroll
        for (int u = 0; u < 2; u++)
            wmma::store_matrix_sync(ep + (wm * 64 + t * 16) * 132 + wn * 32 + u * 16,
                                    acc[t][u], 132, wmma::mem_row_major);
    __syncthreads();

    int which = n0 >> 10;
    __nv_bfloat16* d1 = (which == 0) ? g_q1 : (which == 1) ? g_k1 : g_v1;
    __nv_bfloat16* d2 = (which == 0) ? g_q2 : (which == 1) ? g_k2 : g_v2;
    #pragma unroll
    for (int it = 0; it < 32; it++) {
        int p = it * 256 + threadIdx.x;
        int row = p >> 6, pr = p & 63;
        float a = ep[row * 132 + pr * 2];
        float b2v = ep[row * 132 + pr * 2 + 1];
        uint32_t hi, lo; split2(a, b2v, hi, lo);
        int n = n0 + pr * 2;
        int h = (n >> 6) & 15, dk0 = n & 63;
        int m = m0 + row, bb = m >> 11, s = m & 2047;
        size_t off = (((size_t)(bb * Hh + h)) * Ss + s) * DKk + dk0;
        *(uint32_t*)(d1 + off) = hi;
        *(uint32_t*)(d2 + off) = lo;
    }
}

// ---------------- out GEMM + residual --------------------------------------
__global__ void __launch_bounds__(256, 2) out_wmma_kernel(const float* __restrict__ hidden,
                                                          float* __restrict__ out) {
    extern __shared__ char dyn[];
    AccFrag acc[4][2];
    #pragma unroll
    for (int t = 0; t < 4; t++)
        #pragma unroll
        for (int u = 0; u < 2; u++) wmma::fill_fragment(acc[t][u], 0.0f);

    int n0 = blockIdx.x * 128, m0 = blockIdx.y * 128;
    gemm_wmma_mainloop2(g_c1 + (size_t)m0 * Dd, g_c2 + (size_t)m0 * Dd,
                        g_wo1 + (size_t)n0 * Dd, g_wo2 + (size_t)n0 * Dd, dyn, acc);

    int w = threadIdx.x >> 5;
    int wm = w >> 2, wn = w & 3;
    #pragma unroll
    for (int t = 0; t < 4; t++) {
        int m_sub = m0 + wm * 64 + t * 16;
        #pragma unroll
        for (int u = 0; u < 2; u++) {
            int n_sub = n0 + wn * 32 + u * 16;
            AccFrag hfrag;
            wmma::load_matrix_sync(hfrag, hidden + (size_t)m_sub * Dd + n_sub, Dd,
                                   wmma::mem_row_major);
            #pragma unroll
            for (int e = 0; e < hfrag.num_elements; e++)
                acc[t][u].x[e] += hfrag.x[e];
            wmma::store_matrix_sync(out + (size_t)m_sub * Dd + n_sub, acc[t][u], Dd,
                                    wmma::mem_row_major);
        }
    }
}

// ==================== K3: WMMA flash attention v11 =========================
// kv-tile 64, smem 112KB, regs capped for 2 CTAs/SM. Fragment-resident
// softmax (v10 structure), warp tiles: QK 32q x 32kv, PV 32q x 32d.
#define PROW 72
#define AQ1 0
#define AQ2 18432
#define AK1 36864
#define AK2 46080
#define AV1 55296
#define AV2 64512
#define AP1 73728
#define AP2 92160
#define ABI 110592
#define ASCL 111360
#define AMR  111872
#define ASMX 112384
#define ASUM 113408
#define ATT_SMEM 114432

__global__ void __launch_bounds__(256, 2) attn_wmma_kernel() {
    extern __shared__ char dyn[];
    __nv_bfloat16* Q1 = (__nv_bfloat16*)(dyn + AQ1);   // [128][72]
    __nv_bfloat16* Q2 = (__nv_bfloat16*)(dyn + AQ2);
    __nv_bfloat16* K1 = (__nv_bfloat16*)(dyn + AK1);   // [64][72]
    __nv_bfloat16* K2 = (__nv_bfloat16*)(dyn + AK2);
    __nv_bfloat16* V1 = (__nv_bfloat16*)(dyn + AV1);   // [64][72]
    __nv_bfloat16* V2 = (__nv_bfloat16*)(dyn + AV2);
    __nv_bfloat16* P1 = (__nv_bfloat16*)(dyn + AP1);   // [128][72]
    __nv_bfloat16* P2 = (__nv_bfloat16*)(dyn + AP2);
    float* bias_s = (float*)(dyn + ABI);               // [192]
    float* scl  = (float*)(dyn + ASCL);                // [128]
    float* mrow_s = (float*)(dyn + AMR);               // [128]
    float* smax = (float*)(dyn + ASMX);                // [128][2]
    float* ssum = (float*)(dyn + ASUM);                // [128][2]

    int tid = threadIdx.x;
    int w = tid >> 5;
    int lane = tid & 31;
    int g4 = lane >> 2, tg = lane & 3;
    int wmq = w >> 1, wnq = w & 1;     // QK/PV: 32q x 32(kv|d)
    int r = tid >> 1, half = tid & 1;
    int qb = gridDim.x - 1 - blockIdx.x;
    int q0 = qb * 128;
    int h  = blockIdx.y;
    int b  = blockIdx.z;
    size_t hoff = ((size_t)(b * Hh + h)) * Ss * DKk;
    const __nv_bfloat16* Qg1 = g_q1 + hoff;
    const __nv_bfloat16* Qg2 = g_q2 + hoff;
    const __nv_bfloat16* Kg1 = g_k1 + hoff;
    const __nv_bfloat16* Kg2 = g_k2 + hoff;
    const __nv_bfloat16* Vg1 = g_v1 + hoff;
    const __nv_bfloat16* Vg2 = g_v2 + hoff;
    const float* biasH = g_bias + h * Ss;

    #pragma unroll
    for (int i = 0; i < 4; i++) {
        int idx = i * 256 + tid;
        int row = idx >> 3, c8 = (idx & 7) * 8;
        *(uint4*)(Q1 + row * 72 + c8) = *(const uint4*)(Qg1 + (size_t)(q0 + row) * DKk + c8);
        *(uint4*)(Q2 + row * 72 + c8) = *(const uint4*)(Qg2 + (size_t)(q0 + row) * DKk + c8);
    }
    float m_r = -INFINITY, l_r = 0.f;
    AccFrag oacc[2][2];
    #pragma unroll
    for (int t = 0; t < 2; t++)
        #pragma unroll
        for (int u = 0; u < 2; u++) wmma::fill_fragment(oacc[t][u], 0.0f);
    __syncthreads();

    int ntiles = 2 * qb + 2;
    for (int kt = 0; kt < ntiles; kt++) {
        int k0 = kt * 64;
        // stage K,V: 64 rows x 64 cols each, 2 uint4 per thread per array
        #pragma unroll
        for (int i = 0; i < 2; i++) {
            int idx = i * 256 + tid;
            int row = idx >> 3, c8 = (idx & 7) * 8;
            size_t goff = (size_t)(k0 + row) * DKk + c8;
            int soff = row * 72 + c8;
            *(uint4*)(K1 + soff) = *(const uint4*)(Kg1 + goff);
            *(uint4*)(K2 + soff) = *(const uint4*)(Kg2 + goff);
            *(uint4*)(V1 + soff) = *(const uint4*)(Vg1 + goff);
            *(uint4*)(V2 + soff) = *(const uint4*)(Vg2 + goff);
        }
        if (tid < 192) {
            int dist = q0 - k0 - 63 + tid;
            bias_s[tid] = biasH[dist < 0 ? 0 : dist];
        }
        __syncthreads();

        // ---- QK with fused bias+mask+row-max (fragments in registers) ----
        bool domask = (kt >= 2 * qb);
        AccFrag sacc[2][2];
        {
            #pragma unroll
            for (int t = 0; t < 2; t++)
                #pragma unroll
                for (int u = 0; u < 2; u++) wmma::fill_fragment(sacc[t][u], 0.0f);
            #pragma unroll
            for (int kk = 0; kk < 4; kk++) {
                wmma::fragment<wmma::matrix_b, 16, 16, 16, __nv_bfloat16, wmma::col_major> b1[2], b2[2];
                #pragma unroll
                for (int u = 0; u < 2; u++) {
                    int bb = (wnq * 32 + u * 16) * 72 + kk * 16;
                    wmma::load_matrix_sync(b1[u], K1 + bb, 72);
                    wmma::load_matrix_sync(b2[u], K2 + bb, 72);
                }
                #pragma unroll
                for (int t = 0; t < 2; t++) {
                    wmma::fragment<wmma::matrix_a, 16, 16, 16, __nv_bfloat16, wmma::row_major> a1, a2;
                    int ab = (wmq * 32 + t * 16) * 72 + kk * 16;
                    wmma::load_matrix_sync(a1, Q1 + ab, 72);
                    wmma::load_matrix_sync(a2, Q2 + ab, 72);
                    #pragma unroll
                    for (int u = 0; u < 2; u++) {
                        wmma::mma_sync(sacc[t][u], a1, b1[u], sacc[t][u]);
                        wmma::mma_sync(sacc[t][u], a1, b2[u], sacc[t][u]);
                        wmma::mma_sync(sacc[t][u], a2, b1[u], sacc[t][u]);
                    }
                }
            }
            #pragma unroll
            for (int t = 0; t < 2; t++) {
                int row0 = wmq * 32 + t * 16 + g4;
                int row1 = row0 + 8;
                int lim0 = row0 + q0 - k0;
                int lim1 = row1 + q0 - k0;
                float mx0 = -INFINITY, mx1 = -INFINITY;
                #pragma unroll
                for (int u = 0; u < 2; u++) {
                    float* xp = sacc[t][u].x;
                    int c0 = wnq * 32 + u * 16 + 2 * tg;
                    int b00 = row0 - c0 + 63;
                    int b10 = row1 - c0 + 63;
                    xp[0] += bias_s[b00];     xp[1] += bias_s[b00 - 1];
                    xp[4] += bias_s[b00 - 8]; xp[5] += bias_s[b00 - 9];
                    xp[2] += bias_s[b10];     xp[3] += bias_s[b10 - 1];
                    xp[6] += bias_s[b10 - 8]; xp[7] += bias_s[b10 - 9];
                    if (domask) {
                        if (c0     > lim0) xp[0] = NEG_BIG;
                        if (c0 + 1 > lim0) xp[1] = NEG_BIG;
                        if (c0 + 8 > lim0) xp[4] = NEG_BIG;
                        if (c0 + 9 > lim0) xp[5] = NEG_BIG;
                        if (c0     > lim1) xp[2] = NEG_BIG;
                        if (c0 + 1 > lim1) xp[3] = NEG_BIG;
                        if (c0 + 8 > lim1) xp[6] = NEG_BIG;
                        if (c0 + 9 > lim1) xp[7] = NEG_BIG;
                    }
                    mx0 = fmaxf(mx0, fmaxf(fmaxf(xp[0], xp[1]), fmaxf(xp[4], xp[5])));
                    mx1 = fmaxf(mx1, fmaxf(fmaxf(xp[2], xp[3]), fmaxf(xp[6], xp[7])));
                }
                mx0 = fmaxf(mx0, __shfl_xor_sync(0xffffffffu, mx0, 1));
                mx0 = fmaxf(mx0, __shfl_xor_sync(0xffffffffu, mx0, 2));
                mx1 = fmaxf(mx1, __shfl_xor_sync(0xffffffffu, mx1, 1));
                mx1 = fmaxf(mx1, __shfl_xor_sync(0xffffffffu, mx1, 2));
                if (tg == 0) {
                    smax[row0 * 2 + wnq] = mx0;
                    smax[row1 * 2 + wnq] = mx1;
                }
            }
        }
        __syncthreads();

        // ---- pass1-lite ----
        {
            float mx = fmaxf(smax[r * 2 + 0], smax[r * 2 + 1]);
            float mnew = fmaxf(m_r, mx);
            float scale = __expf(m_r - mnew);
            m_r = mnew;
            l_r *= scale;
            if (half == 0) { scl[r] = scale; mrow_s[r] = mnew; }
        }
        __syncthreads();

        // ---- rescale persistent O fragments ----
        #pragma unroll
        for (int t = 0; t < 2; t++) {
            int base = wmq * 32 + t * 16;
            float s0 = scl[base + g4];
            float s1 = scl[base + g4 + 8];
            #pragma unroll
            for (int u = 0; u < 2; u++) {
                oacc[t][u].x[0] *= s0; oacc[t][u].x[1] *= s0;
                oacc[t][u].x[4] *= s0; oacc[t][u].x[5] *= s0;
                oacc[t][u].x[2] *= s1; oacc[t][u].x[3] *= s1;
                oacc[t][u].x[6] *= s1; oacc[t][u].x[7] *= s1;
            }
        }

        // ---- exp in fragments, split-store P, partial rowsums ----
        #pragma unroll
        for (int t = 0; t < 2; t++) {
            int row0 = wmq * 32 + t * 16 + g4;
            int row1 = row0 + 8;
            float m0 = mrow_s[row0];
            float m1 = mrow_s[row1];
            float rs0 = 0.f, rs1 = 0.f;
            #pragma unroll
            for (int u = 0; u < 2; u++) {
                float* xp = sacc[t][u].x;
                int c0 = wnq * 32 + u * 16 + 2 * tg;
                float p0 = __expf(xp[0] - m0), p1 = __expf(xp[1] - m0);
                float p4 = __expf(xp[4] - m0), p5 = __expf(xp[5] - m0);
                float p2 = __expf(xp[2] - m1), p3 = __expf(xp[3] - m1);
                float p6 = __expf(xp[6] - m1), p7 = __expf(xp[7] - m1);
                rs0 += (p0 + p1) + (p4 + p5);
                rs1 += (p2 + p3) + (p6 + p7);
                uint32_t hi, lo;
                split2(p0, p1, hi, lo);
                *(uint32_t*)(P1 + row0 * PROW + c0) = hi;
                *(uint32_t*)(P2 + row0 * PROW + c0) = lo;
                split2(p4, p5, hi, lo);
                *(uint32_t*)(P1 + row0 * PROW + c0 + 8) = hi;
                *(uint32_t*)(P2 + row0 * PROW + c0 + 8) = lo;
                split2(p2, p3, hi, lo);
                *(uint32_t*)(P1 + row1 * PROW + c0) = hi;
                *(uint32_t*)(P2 + row1 * PROW + c0) = lo;
                split2(p6, p7, hi, lo);
                *(uint32_t*)(P1 + row1 * PROW + c0 + 8) = hi;
                *(uint32_t*)(P2 + row1 * PROW + c0 + 8) = lo;
            }
            rs0 += __shfl_xor_sync(0xffffffffu, rs0, 1);
            rs0 += __shfl_xor_sync(0xffffffffu, rs0, 2);
            rs1 += __shfl_xor_sync(0xffffffffu, rs1, 1);
            rs1 += __shfl_xor_sync(0xffffffffu, rs1, 2);
            if (tg == 0) {
                ssum[row0 * 2 + wnq] = rs0;
                ssum[row1 * 2 + wnq] = rs1;
            }
        }
        __syncthreads();

        // ---- l update + PV over 64-kv P ----
        l_r += ssum[r * 2 + 0] + ssum[r * 2 + 1];
        #pragma unroll
        for (int kk = 0; kk < 4; kk++) {
            wmma::fragment<wmma::matrix_a, 16, 16, 16, __nv_bfloat16, wmma::row_major> a1[2], a2[2];
            #pragma unroll
            for (int t = 0; t < 2; t++) {
                int ab = (wmq * 32 + t * 16) * PROW + kk * 16;
                wmma::load_matrix_sync(a1[t], P1 + ab, PROW);
                wmma::load_matrix_sync(a2[t], P2 + ab, PROW);
            }
            #pragma unroll
            for (int u = 0; u < 2; u++) {
                wmma::fragment<wmma::matrix_b, 16, 16, 16, __nv_bfloat16, wmma::row_major> b1, b2;
                int bb = (kk * 16) * 72 + wnq * 32 + u * 16;
                wmma::load_matrix_sync(b1, V1 + bb, 72);
                wmma::load_matrix_sync(b2, V2 + bb, 72);
                #pragma unroll
                for (int t = 0; t < 2; t++) {
                    wmma::mma_sync(oacc[t][u], a1[t], b1, oacc[t][u]);
                    wmma::mma_sync(oacc[t][u], a1[t], b2, oacc[t][u]);
                    wmma::mma_sync(oacc[t][u], a2[t], b1, oacc[t][u]);
                }
            }
        }
        __syncthreads();   // P/V consumed before next tile staging
    }

    // epilogue: dump O fragments into dead Q/K region as float ep[128][132]
    float* ep = (float*)dyn;
    #pragma unroll
    for (int t = 0; t < 2; t++)
        #pragma unroll
        for (int u = 0; u < 2; u++)
            wmma::store_matrix_sync(ep + (wmq * 32 + t * 16) * 132 + wnq * 32 + u * 16,
                                    oacc[t][u], 132, wmma::mem_row_major);
    __syncthreads();
    float inv = 1.0f / l_r;
    size_t cbase = ((size_t)(b * Ss + q0 + r)) * Dd + h * DKk + half * 32;
    {
        float* Sr = ep + r * 132 + half * 32;
        #pragma unroll
        for (int c4 = 0; c4 < 32; c4 += 4) {
            float v0 = Sr[c4] * inv,     v1 = Sr[c4 + 1] * inv;
            float v2 = Sr[c4 + 2] * inv, v3 = Sr[c4 + 3] * inv;
            uint32_t h0, l0, h1, l1;
            split2(v0, v1, h0, l0);
            split2(v2, v3, h1, l1);
            *(uint2*)(g_c1 + cbase + c4) = make_uint2(h0, h1);
            *(uint2*)(g_c2 + cbase + c4) = make_uint2(l0, l1);
        }
    }
}

// ==================== launch ==============================================
extern "C" void kernel_launch(void* const* d_in, const int* in_sizes, int n_in,
                              void* d_out, int out_size) {
    const float* hidden   = (const float*)d_in[0];
    const float* rms_w    = (const float*)d_in[2];
    const float* W_qkv    = (const float*)d_in[3];
    const float* W_o      = (const float*)d_in[4];
    const float* rel_bias = (const float*)d_in[5];
    float* out = (float*)d_out;

    rmsnorm_kernel<<<Bb * Ss, 256>>>(hidden, rms_w);
    bias_table_kernel<<<dim3(Ss / 256, Hh), 256>>>(rel_bias);
    tsplit_wq_kernel<<<dim3(3072 / 32, Dd / 32), 256>>>(W_qkv);
    tsplit_wo_kernel<<<dim3(Dd / 32, Dd / 32), 256>>>(W_o);

    cudaFuncSetAttribute(qkv_wmma_kernel, cudaFuncAttributeMaxDynamicSharedMemorySize, DYN_SMEM);
    qkv_wmma_kernel<<<dim3(3072 / 128, (Bb * Ss) / 128), 256, DYN_SMEM>>>();

    cudaFuncSetAttribute(attn_wmma_kernel, cudaFuncAttributeMaxDynamicSharedMemorySize, ATT_SMEM);
    attn_wmma_kernel<<<dim3(Ss / 128, Hh, Bb), 256, ATT_SMEM>>>();

    cudaFuncSetAttribute(out_wmma_kernel, cudaFuncAttributeMaxDynamicSharedMemorySize, DYN_SMEM);
    out_wmma_kernel<<<dim3(Dd / 128, (Bb * Ss) / 128), 256, DYN_SMEM>>>(hidden, out);
}